// round 1
// baseline (speedup 1.0000x reference)
#include <cuda_runtime.h>

#define NN 20000
#define NE 320000
#define CC 64
#define PL (NN*CC)          // one plane of agg: [NN, 64]

// Scratch (allocation-free rule: __device__ globals)
__device__ __align__(16) float g_h[NN*CC];        // 5.1 MB
__device__ __align__(16) float g_agg[9*PL];       // 46 MB, 9 planes

__device__ __forceinline__ float silu(float x) {
    return x * (1.0f / (1.0f + __expf(-x)));
}

__device__ __forceinline__ void red4(float* p, float a, float b, float c, float d) {
    asm volatile("red.global.add.v4.f32 [%0], {%1,%2,%3,%4};"
                 :: "l"(p), "f"(a), "f"(b), "f"(c), "f"(d) : "memory");
}

// ---------------------------------------------------------------- zero agg
__global__ void zero_kernel() {
    int i = blockIdx.x * blockDim.x + threadIdx.x;
    float4* p = (float4*)g_agg;
    const int n4 = 9 * PL / 4;
    if (i < n4) p[i] = make_float4(0.f, 0.f, 0.f, 0.f);
}

// ---------------------------------------------------------------- h = nf @ w_up * (1/8)
__global__ void up_kernel(const float* __restrict__ nf, const float* __restrict__ wup) {
    __shared__ float ws[CC*CC];
    __shared__ float rows[4*CC];
    for (int i = threadIdx.x; i < CC*CC; i += blockDim.x) ws[i] = wup[i];
    int base = blockIdx.x * 4 * CC;
    rows[threadIdx.x] = nf[base + threadIdx.x];
    __syncthreads();
    int r = threadIdx.x >> 6;
    int c = threadIdx.x & 63;
    float acc = 0.f;
    #pragma unroll 16
    for (int i = 0; i < CC; i++) acc = fmaf(rows[r*CC + i], ws[i*CC + c], acc);
    g_h[base + threadIdx.x] = acc * 0.125f;
}

// ---------------------------------------------------------------- edge kernel
// one edge per thread; weights in shared; MLP in registers; streamed L4 + v4 scatter
__global__ __launch_bounds__(128) void edge_kernel(
    const float* __restrict__ vectors, const float* __restrict__ radial,
    const int* __restrict__ senders, const int* __restrict__ receivers,
    const float* __restrict__ w1, const float* __restrict__ w2,
    const float* __restrict__ w3, const float* __restrict__ w4)
{
    extern __shared__ float smem[];
    float* s1 = smem;               // 8*64   = 512
    float* s2 = s1 + 512;           // 64*64  = 4096
    float* s3 = s2 + 4096;          // 64*64  = 4096
    float* s4 = s3 + 4096;          // 64*192 = 12288   (total 20992 floats = 84 KB)
    {
        float4* d; const float4* s;
        d = (float4*)s1; s = (const float4*)w1;
        for (int i = threadIdx.x; i < 128;  i += 128) d[i] = s[i];
        d = (float4*)s2; s = (const float4*)w2;
        for (int i = threadIdx.x; i < 1024; i += 128) d[i] = s[i];
        d = (float4*)s3; s = (const float4*)w3;
        for (int i = threadIdx.x; i < 1024; i += 128) d[i] = s[i];
        d = (float4*)s4; s = (const float4*)w4;
        for (int i = threadIdx.x; i < 3072; i += 128) d[i] = s[i];
    }
    __syncthreads();

    const int e = blockIdx.x * 128 + threadIdx.x;   // NE = 2500*128 exactly

    // radial row (32B aligned)
    const float4* rr = (const float4*)(radial + e*8);
    float4 r0 = rr[0], r1 = rr[1];
    float r[8] = {r0.x, r0.y, r0.z, r0.w, r1.x, r1.y, r1.z, r1.w};

    float a[64], b[64];

    // L1: a = silu((r @ w1) / sqrt(8))
    #pragma unroll
    for (int j = 0; j < 64; j += 4) {
        float q0=0.f,q1=0.f,q2=0.f,q3=0.f;
        #pragma unroll
        for (int i = 0; i < 8; i++) {
            float ri = r[i]; const float* w = s1 + i*64 + j;
            q0 = fmaf(ri, w[0], q0); q1 = fmaf(ri, w[1], q1);
            q2 = fmaf(ri, w[2], q2); q3 = fmaf(ri, w[3], q3);
        }
        a[j]   = silu(q0 * 0.35355339f);
        a[j+1] = silu(q1 * 0.35355339f);
        a[j+2] = silu(q2 * 0.35355339f);
        a[j+3] = silu(q3 * 0.35355339f);
    }
    // L2: b = silu((a @ w2) * 0.125)
    #pragma unroll 4
    for (int j = 0; j < 64; j += 4) {
        float q0=0.f,q1=0.f,q2=0.f,q3=0.f;
        #pragma unroll 16
        for (int i = 0; i < 64; i++) {
            float ai = a[i]; const float* w = s2 + i*64 + j;
            q0 = fmaf(ai, w[0], q0); q1 = fmaf(ai, w[1], q1);
            q2 = fmaf(ai, w[2], q2); q3 = fmaf(ai, w[3], q3);
        }
        b[j]   = silu(q0 * 0.125f);
        b[j+1] = silu(q1 * 0.125f);
        b[j+2] = silu(q2 * 0.125f);
        b[j+3] = silu(q3 * 0.125f);
    }
    // L3: a = silu((b @ w3) * 0.125)
    #pragma unroll 4
    for (int j = 0; j < 64; j += 4) {
        float q0=0.f,q1=0.f,q2=0.f,q3=0.f;
        #pragma unroll 16
        for (int i = 0; i < 64; i++) {
            float bi = b[i]; const float* w = s3 + i*64 + j;
            q0 = fmaf(bi, w[0], q0); q1 = fmaf(bi, w[1], q1);
            q2 = fmaf(bi, w[2], q2); q3 = fmaf(bi, w[3], q3);
        }
        a[j]   = silu(q0 * 0.125f);
        a[j+1] = silu(q1 * 0.125f);
        a[j+2] = silu(q2 * 0.125f);
        a[j+3] = silu(q3 * 0.125f);
    }

    // spherical harmonics
    float vx = vectors[e*3], vy = vectors[e*3+1], vz = vectors[e*3+2];
    float inv = rsqrtf(vx*vx + vy*vy + vz*vz);
    float ux = vx*inv, uy = vy*inv, uz = vz*inv;
    const float SQ3 = 1.7320508075688772f, S15 = 3.872983346207417f;
    const float HS5 = 1.118033988749895f;
    float y1v[3] = {SQ3*ux, SQ3*uy, SQ3*uz};
    float y2v[5] = {S15*ux*uy, S15*uy*uz, HS5*(3.f*uz*uz - 1.f),
                    S15*ux*uz, 0.5f*S15*(ux*ux - uy*uy)};

    const int snd = senders[e], rcv = receivers[e];
    const float4* hrow = (const float4*)(g_h + snd*64);
    float* aggb = g_agg + rcv*64;

    const float KSC = 0.125f * (1.0f/64.0f);   // mlp_w4 scale * (1/C)

    // L4 streamed in groups of 4 channels + scatter (9 planes per group, v4 RED)
    #pragma unroll 1
    for (int c = 0; c < 64; c += 4) {
        float d0[4], d1[4], d2[4];
        #pragma unroll
        for (int q = 0; q < 4; q++) {
            float q0=0.f,q1=0.f,q2=0.f;
            #pragma unroll 16
            for (int i = 0; i < 64; i++) {
                float ai = a[i]; const float* w = s4 + i*192 + c + q;
                q0 = fmaf(ai, w[0],   q0);
                q1 = fmaf(ai, w[64],  q1);
                q2 = fmaf(ai, w[128], q2);
            }
            d0[q] = q0; d1[q] = q1; d2[q] = q2;
        }
        float4 sv = hrow[c >> 2];
        float svv[4] = {sv.x, sv.y, sv.z, sv.w};
        float t0[4], t1[4], t2[4];
        #pragma unroll
        for (int q = 0; q < 4; q++) {
            t0[q] = svv[q]*d0[q]*KSC;
            t1[q] = svv[q]*d1[q]*KSC;
            t2[q] = svv[q]*d2[q]*KSC;
        }
        red4(aggb + c, t0[0], t0[1], t0[2], t0[3]);
        #pragma unroll
        for (int m = 0; m < 3; m++) {
            float ym = y1v[m];
            red4(aggb + (1+m)*PL + c, t1[0]*ym, t1[1]*ym, t1[2]*ym, t1[3]*ym);
        }
        #pragma unroll
        for (int m = 0; m < 5; m++) {
            float ym = y2v[m];
            red4(aggb + (4+m)*PL + c, t2[0]*ym, t2[1]*ym, t2[2]*ym, t2[3]*ym);
        }
    }
}

// ---------------------------------------------------------------- down projection
// out[n, 0:64]  = (EPS*a0) @ w0 /8 ; out[n, 64+3d+m] = sum_c a1[c,m] w1[c,d]*EPS/8 ; etc.
__global__ void down_kernel(const float* __restrict__ w0, const float* __restrict__ w1,
                            const float* __restrict__ w2, float* __restrict__ out)
{
    extern __shared__ float dsm[];
    float* sw = dsm;          // 3*4096
    float* sa = dsm + 12288;  // 576
    for (int i = threadIdx.x; i < 4096; i += blockDim.x) {
        sw[i]        = w0[i];
        sw[4096 + i] = w1[i];
        sw[8192 + i] = w2[i];
    }
    const int t = threadIdx.x;   // 0..575
    int plane, d, woff;
    if (t < 64)       { plane = 0;             d = t;                 woff = 0;    }
    else if (t < 256) { int k = t - 64;  d = k/3; plane = 1 + (k - d*3); woff = 4096; }
    else              { int k = t - 256; d = k/5; plane = 4 + (k - d*5); woff = 8192; }

    for (int n = blockIdx.x; n < NN; n += gridDim.x) {
        __syncthreads();
        sa[t] = g_agg[(t >> 6) * PL + n*64 + (t & 63)];
        __syncthreads();
        float acc = 0.f;
        const float* w  = sw + woff + d;
        const float* ap = sa + plane * 64;
        #pragma unroll 16
        for (int c = 0; c < 64; c++) acc = fmaf(ap[c], w[c*64], acc);
        out[n*576 + t] = acc * 0.0625f;   // EPS(0.5) * inv_sqrt_c(0.125)
    }
}

// ---------------------------------------------------------------- launch
extern "C" void kernel_launch(void* const* d_in, const int* in_sizes, int n_in,
                              void* d_out, int out_size)
{
    const float* vectors    = (const float*)d_in[0];
    const float* node_feats = (const float*)d_in[1];
    const float* radial     = (const float*)d_in[2];
    const int*   senders    = (const int*)  d_in[3];
    const int*   receivers  = (const int*)  d_in[4];
    const float* w_up       = (const float*)d_in[5];
    const float* mlp_w1     = (const float*)d_in[6];
    const float* mlp_w2     = (const float*)d_in[7];
    const float* mlp_w3     = (const float*)d_in[8];
    const float* mlp_w4     = (const float*)d_in[9];
    const float* w_down0    = (const float*)d_in[10];
    const float* w_down1    = (const float*)d_in[11];
    const float* w_down2    = (const float*)d_in[12];
    float* out = (float*)d_out;

    const int EDGE_SMEM = 20992 * 4;          // 83968 B
    const int DOWN_SMEM = (12288 + 576) * 4;  // 51456 B
    cudaFuncSetAttribute(edge_kernel, cudaFuncAttributeMaxDynamicSharedMemorySize, EDGE_SMEM);
    cudaFuncSetAttribute(down_kernel, cudaFuncAttributeMaxDynamicSharedMemorySize, DOWN_SMEM);

    const int n4 = 9 * PL / 4;
    zero_kernel<<<(n4 + 255)/256, 256>>>();
    up_kernel<<<NN/4, 256>>>(node_feats, w_up);
    edge_kernel<<<NE/128, 128, EDGE_SMEM>>>(vectors, radial, senders, receivers,
                                            mlp_w1, mlp_w2, mlp_w3, mlp_w4);
    down_kernel<<<2000, 576, DOWN_SMEM>>>(w_down0, w_down1, w_down2, out);
}

// round 2
// speedup vs baseline: 1.8808x; 1.8808x over previous
#include <cuda_runtime.h>

#define NN 20000
#define NE 320000
#define CC 64
#define PL (NN*CC)          // one plane of agg: [NN, 64]

typedef unsigned long long ull;

// Scratch (allocation-free rule: __device__ globals)
__device__ __align__(16) float g_h[NN*CC];        // 5.1 MB
__device__ __align__(16) float g_agg[9*PL];       // 46 MB, 9 planes

__device__ __forceinline__ float silu(float x) {
    return x * (1.0f / (1.0f + __expf(-x)));
}

__device__ __forceinline__ ull pack2(float x) {
    ull r; asm("mov.b64 %0, {%1, %1};" : "=l"(r) : "f"(x)); return r;
}
__device__ __forceinline__ void ffma2(ull& q, ull w, ull a) {
    asm("fma.rn.f32x2 %0, %1, %2, %0;" : "+l"(q) : "l"(w), "l"(a));
}
__device__ __forceinline__ float2 unpk(ull v) {
    float lo, hi; asm("mov.b64 {%0, %1}, %2;" : "=f"(lo), "=f"(hi) : "l"(v));
    return make_float2(lo, hi);
}
__device__ __forceinline__ void red4(float* p, float a, float b, float c, float d) {
    asm volatile("red.global.add.v4.f32 [%0], {%1,%2,%3,%4};"
                 :: "l"(p), "f"(a), "f"(b), "f"(c), "f"(d) : "memory");
}

// ---------------------------------------------------------------- zero agg
__global__ void zero_kernel() {
    int i = blockIdx.x * blockDim.x + threadIdx.x;
    float4* p = (float4*)g_agg;
    const int n4 = 9 * PL / 4;
    if (i < n4) p[i] = make_float4(0.f, 0.f, 0.f, 0.f);
}

// ---------------------------------------------------------------- h = nf @ w_up * (1/8)
__global__ void up_kernel(const float* __restrict__ nf, const float* __restrict__ wup) {
    __shared__ float ws[CC*CC];
    __shared__ float rows[4*CC];
    for (int i = threadIdx.x; i < CC*CC; i += blockDim.x) ws[i] = wup[i];
    int base = blockIdx.x * 4 * CC;
    rows[threadIdx.x] = nf[base + threadIdx.x];
    __syncthreads();
    int r = threadIdx.x >> 6;
    int c = threadIdx.x & 63;
    float acc = 0.f;
    #pragma unroll
    for (int i = 0; i < CC; i++) acc = fmaf(rows[r*CC + i], ws[i*CC + c], acc);
    g_h[base + threadIdx.x] = acc * 0.125f;
}

// ---------------------------------------------------------------- 64->64 MLP layer, packed f32x2
// a[64] in registers (static indices only). w in shared (broadcast loads).
__device__ __forceinline__ void layer64(const float* __restrict__ w, float a[64], float scale) {
    ull q[32];
    #pragma unroll
    for (int p = 0; p < 32; p++) q[p] = 0ull;
    #pragma unroll
    for (int i = 0; i < 64; i++) {
        ull a2 = pack2(a[i]);
        const ulonglong2* wr = (const ulonglong2*)(w + i*64);
        #pragma unroll
        for (int t = 0; t < 16; t++) {
            ulonglong2 wp = wr[t];
            ffma2(q[2*t],   wp.x, a2);
            ffma2(q[2*t+1], wp.y, a2);
        }
    }
    #pragma unroll
    for (int p = 0; p < 32; p++) {
        float2 f = unpk(q[p]);
        a[2*p]   = silu(f.x * scale);
        a[2*p+1] = silu(f.y * scale);
    }
}

// ---------------------------------------------------------------- L4 pass: 16 channels (48 outputs) + scatter
__device__ __forceinline__ void l4pass(const float* __restrict__ s4, const float a[64], int c0,
                                       const float4* __restrict__ hrow, float* __restrict__ aggb,
                                       const float y1v[3], const float y2v[5]) {
    const float KSC = 0.125f * (1.0f/64.0f);   // mlp_w4 scale * (1/C)
    ull p0[8], p1[8], p2[8];
    #pragma unroll
    for (int k = 0; k < 8; k++) { p0[k] = 0ull; p1[k] = 0ull; p2[k] = 0ull; }
    #pragma unroll
    for (int i = 0; i < 64; i++) {
        ull a2 = pack2(a[i]);
        const ulonglong2* wa = (const ulonglong2*)(s4 + i*192 + c0);
        const ulonglong2* wb = (const ulonglong2*)(s4 + i*192 + 64 + c0);
        const ulonglong2* wc = (const ulonglong2*)(s4 + i*192 + 128 + c0);
        #pragma unroll
        for (int t = 0; t < 4; t++) {
            ulonglong2 w0 = wa[t]; ffma2(p0[2*t], w0.x, a2); ffma2(p0[2*t+1], w0.y, a2);
            ulonglong2 w1 = wb[t]; ffma2(p1[2*t], w1.x, a2); ffma2(p1[2*t+1], w1.y, a2);
            ulonglong2 w2 = wc[t]; ffma2(p2[2*t], w2.x, a2); ffma2(p2[2*t+1], w2.y, a2);
        }
    }
    #pragma unroll
    for (int k = 0; k < 4; k++) {
        float4 sv = hrow[(c0 >> 2) + k];
        float2 f0a = unpk(p0[2*k]), f0b = unpk(p0[2*k+1]);
        float2 f1a = unpk(p1[2*k]), f1b = unpk(p1[2*k+1]);
        float2 f2a = unpk(p2[2*k]), f2b = unpk(p2[2*k+1]);
        float t0[4] = { sv.x*f0a.x*KSC, sv.y*f0a.y*KSC, sv.z*f0b.x*KSC, sv.w*f0b.y*KSC };
        float t1[4] = { sv.x*f1a.x*KSC, sv.y*f1a.y*KSC, sv.z*f1b.x*KSC, sv.w*f1b.y*KSC };
        float t2[4] = { sv.x*f2a.x*KSC, sv.y*f2a.y*KSC, sv.z*f2b.x*KSC, sv.w*f2b.y*KSC };
        float* base = aggb + c0 + 4*k;
        red4(base, t0[0], t0[1], t0[2], t0[3]);
        #pragma unroll
        for (int m = 0; m < 3; m++) {
            float ym = y1v[m];
            red4(base + (1+m)*PL, t1[0]*ym, t1[1]*ym, t1[2]*ym, t1[3]*ym);
        }
        #pragma unroll
        for (int m = 0; m < 5; m++) {
            float ym = y2v[m];
            red4(base + (4+m)*PL, t2[0]*ym, t2[1]*ym, t2[2]*ym, t2[3]*ym);
        }
    }
}

// ---------------------------------------------------------------- edge kernel
__global__ __launch_bounds__(128) void edge_kernel(
    const float* __restrict__ vectors, const float* __restrict__ radial,
    const int* __restrict__ senders, const int* __restrict__ receivers,
    const float* __restrict__ w1, const float* __restrict__ w2,
    const float* __restrict__ w3, const float* __restrict__ w4)
{
    extern __shared__ float smem[];
    float* s1 = smem;               // 8*64   = 512
    float* s2 = s1 + 512;           // 64*64  = 4096
    float* s3 = s2 + 4096;          // 64*64  = 4096
    float* s4 = s3 + 4096;          // 64*192 = 12288   (total 20992 floats = 84 KB)
    {
        float4* d; const float4* s;
        d = (float4*)s1; s = (const float4*)w1;
        for (int i = threadIdx.x; i < 128;  i += 128) d[i] = s[i];
        d = (float4*)s2; s = (const float4*)w2;
        for (int i = threadIdx.x; i < 1024; i += 128) d[i] = s[i];
        d = (float4*)s3; s = (const float4*)w3;
        for (int i = threadIdx.x; i < 1024; i += 128) d[i] = s[i];
        d = (float4*)s4; s = (const float4*)w4;
        for (int i = threadIdx.x; i < 3072; i += 128) d[i] = s[i];
    }
    __syncthreads();

    const int e = blockIdx.x * 128 + threadIdx.x;   // NE = 2500*128 exactly

    // radial row (32B aligned)
    const float4* rr = (const float4*)(radial + e*8);
    float4 r0 = rr[0], r1 = rr[1];
    float rv[8] = {r0.x, r0.y, r0.z, r0.w, r1.x, r1.y, r1.z, r1.w};

    float a[64];

    // L1: a = silu((r @ w1) / sqrt(8)), packed
    {
        ull q[32];
        #pragma unroll
        for (int p = 0; p < 32; p++) q[p] = 0ull;
        #pragma unroll
        for (int i = 0; i < 8; i++) {
            ull a2 = pack2(rv[i]);
            const ulonglong2* wr = (const ulonglong2*)(s1 + i*64);
            #pragma unroll
            for (int t = 0; t < 16; t++) {
                ulonglong2 wp = wr[t];
                ffma2(q[2*t],   wp.x, a2);
                ffma2(q[2*t+1], wp.y, a2);
            }
        }
        #pragma unroll
        for (int p = 0; p < 32; p++) {
            float2 f = unpk(q[p]);
            a[2*p]   = silu(f.x * 0.35355339059f);
            a[2*p+1] = silu(f.y * 0.35355339059f);
        }
    }

    layer64(s2, a, 0.125f);   // L2
    layer64(s3, a, 0.125f);   // L3

    // spherical harmonics
    float vx = vectors[e*3], vy = vectors[e*3+1], vz = vectors[e*3+2];
    float inv = rsqrtf(vx*vx + vy*vy + vz*vz);
    float ux = vx*inv, uy = vy*inv, uz = vz*inv;
    const float SQ3 = 1.7320508075688772f, S15 = 3.872983346207417f;
    const float HS5 = 1.118033988749895f;
    float y1v[3] = {SQ3*ux, SQ3*uy, SQ3*uz};
    float y2v[5] = {S15*ux*uy, S15*uy*uz, HS5*(3.f*uz*uz - 1.f),
                    S15*ux*uz, 0.5f*S15*(ux*ux - uy*uy)};

    const int snd = senders[e], rcv = receivers[e];
    const float4* hrow = (const float4*)(g_h + snd*64);
    float* aggb = g_agg + rcv*64;

    // L4 in 4 passes of 16 channels, scatter fused
    l4pass(s4, a, 0,  hrow, aggb, y1v, y2v);
    l4pass(s4, a, 16, hrow, aggb, y1v, y2v);
    l4pass(s4, a, 32, hrow, aggb, y1v, y2v);
    l4pass(s4, a, 48, hrow, aggb, y1v, y2v);
}

// ---------------------------------------------------------------- down projection
// out[n, t]: weights live in registers (fixed per thread), activations broadcast from shared.
#define DOWN_NODES_PER_BLOCK 20
__global__ __launch_bounds__(576) void down_kernel(const float* __restrict__ w0, const float* __restrict__ w1,
                                                   const float* __restrict__ w2, float* __restrict__ out)
{
    extern __shared__ float dsm[];
    float* sw = dsm;          // 3*4096
    float* sa = dsm + 12288;  // 640 (576 used)
    for (int i = threadIdx.x; i < 4096; i += blockDim.x) {
        sw[i]        = w0[i];
        sw[4096 + i] = w1[i];
        sw[8192 + i] = w2[i];
    }
    const int t = threadIdx.x;   // 0..575
    int plane, d, woff;
    if (t < 64)       { plane = 0;               d = t;                   woff = 0;    }
    else if (t < 256) { int k = t - 64;  d = k/3; plane = 1 + (k - d*3);   woff = 4096; }
    else              { int k = t - 256; d = k/5; plane = 4 + (k - d*5);   woff = 8192; }
    __syncthreads();

    float wreg[64];
    #pragma unroll
    for (int c = 0; c < 64; c++) wreg[c] = sw[woff + c*64 + d];

    const int n0 = blockIdx.x * DOWN_NODES_PER_BLOCK;
    for (int n = n0; n < n0 + DOWN_NODES_PER_BLOCK; n++) {
        __syncthreads();
        sa[t] = g_agg[(t >> 6) * PL + n*64 + (t & 63)];
        __syncthreads();
        const float4* ap4 = (const float4*)(sa + plane*64);
        float acc = 0.f;
        #pragma unroll
        for (int cg = 0; cg < 16; cg++) {
            float4 v = ap4[cg];
            acc = fmaf(v.x, wreg[4*cg],   acc);
            acc = fmaf(v.y, wreg[4*cg+1], acc);
            acc = fmaf(v.z, wreg[4*cg+2], acc);
            acc = fmaf(v.w, wreg[4*cg+3], acc);
        }
        out[n*576 + t] = acc * 0.0625f;   // EPS(0.5) * inv_sqrt_c(0.125)
    }
}

// ---------------------------------------------------------------- launch
extern "C" void kernel_launch(void* const* d_in, const int* in_sizes, int n_in,
                              void* d_out, int out_size)
{
    const float* vectors    = (const float*)d_in[0];
    const float* node_feats = (const float*)d_in[1];
    const float* radial     = (const float*)d_in[2];
    const int*   senders    = (const int*)  d_in[3];
    const int*   receivers  = (const int*)  d_in[4];
    const float* w_up       = (const float*)d_in[5];
    const float* mlp_w1     = (const float*)d_in[6];
    const float* mlp_w2     = (const float*)d_in[7];
    const float* mlp_w3     = (const float*)d_in[8];
    const float* mlp_w4     = (const float*)d_in[9];
    const float* w_down0    = (const float*)d_in[10];
    const float* w_down1    = (const float*)d_in[11];
    const float* w_down2    = (const float*)d_in[12];
    float* out = (float*)d_out;

    const int EDGE_SMEM = 20992 * 4;          // 83968 B
    const int DOWN_SMEM = (12288 + 640) * 4;  // 51712 B
    cudaFuncSetAttribute(edge_kernel, cudaFuncAttributeMaxDynamicSharedMemorySize, EDGE_SMEM);
    cudaFuncSetAttribute(down_kernel, cudaFuncAttributeMaxDynamicSharedMemorySize, DOWN_SMEM);

    const int n4 = 9 * PL / 4;
    zero_kernel<<<(n4 + 255)/256, 256>>>();
    up_kernel<<<NN/4, 256>>>(node_feats, w_up);
    edge_kernel<<<NE/128, 128, EDGE_SMEM>>>(vectors, radial, senders, receivers,
                                            mlp_w1, mlp_w2, mlp_w3, mlp_w4);
    down_kernel<<<NN/DOWN_NODES_PER_BLOCK, 576, DOWN_SMEM>>>(w_down0, w_down1, w_down2, out);
}

// round 3
// speedup vs baseline: 2.4126x; 1.2827x over previous
#include <cuda_runtime.h>

#define NN 20000
#define NE 320000
#define CC 64
#define PL (NN*CC)          // one plane of agg: [NN, 64]

typedef unsigned long long ull;

// Scratch (allocation-free rule: __device__ globals)
__device__ __align__(16) float g_h[NN*CC];        // 5.1 MB
__device__ __align__(16) float g_agg[9*PL];       // 46 MB, 9 planes
__device__ __align__(16) float g_act[NE*CC];      // 82 MB, edge MLP activations

__device__ __forceinline__ float silu(float x) {
    return x * (1.0f / (1.0f + __expf(-x)));
}
__device__ __forceinline__ ull pack2(float x) {
    ull r; asm("mov.b64 %0, {%1, %1};" : "=l"(r) : "f"(x)); return r;
}
__device__ __forceinline__ void ffma2(ull& q, ull w, ull a) {
    asm("fma.rn.f32x2 %0, %1, %2, %0;" : "+l"(q) : "l"(w), "l"(a));
}
__device__ __forceinline__ float2 unpk(ull v) {
    float lo, hi; asm("mov.b64 {%0, %1}, %2;" : "=f"(lo), "=f"(hi) : "l"(v));
    return make_float2(lo, hi);
}
__device__ __forceinline__ void red4(float* p, float a, float b, float c, float d) {
    asm volatile("red.global.add.v4.f32 [%0], {%1,%2,%3,%4};"
                 :: "l"(p), "f"(a), "f"(b), "f"(c), "f"(d) : "memory");
}

// ---------------------------------------------------------------- h = nf @ w_up * (1/8)
__global__ void up_kernel(const float* __restrict__ nf, const float* __restrict__ wup) {
    __shared__ float ws[CC*CC];
    __shared__ float rows[4*CC];
    for (int i = threadIdx.x; i < CC*CC; i += blockDim.x) ws[i] = wup[i];
    int base = blockIdx.x * 4 * CC;
    rows[threadIdx.x] = nf[base + threadIdx.x];
    __syncthreads();
    int r = threadIdx.x >> 6;
    int c = threadIdx.x & 63;
    float acc = 0.f;
    #pragma unroll
    for (int i = 0; i < CC; i++) acc = fmaf(rows[r*CC + i], ws[i*CC + c], acc);
    g_h[base + threadIdx.x] = acc * 0.125f;
}

// ---------------------------------------------------------------- 64->64 MLP layer, packed f32x2
__device__ __forceinline__ void layer64(const float* __restrict__ w, float a[64], float scale) {
    ull q[32];
    #pragma unroll
    for (int p = 0; p < 32; p++) q[p] = 0ull;
    #pragma unroll
    for (int i = 0; i < 64; i++) {
        ull a2 = pack2(a[i]);
        const ulonglong2* wr = (const ulonglong2*)(w + i*64);
        #pragma unroll
        for (int t = 0; t < 16; t++) {
            ulonglong2 wp = wr[t];
            ffma2(q[2*t],   wp.x, a2);
            ffma2(q[2*t+1], wp.y, a2);
        }
    }
    #pragma unroll
    for (int p = 0; p < 32; p++) {
        float2 f = unpk(q[p]);
        a[2*p]   = silu(f.x * scale);
        a[2*p+1] = silu(f.y * scale);
    }
}

// ---------------------------------------------------------------- edge A: radial MLP L1-L3 -> g_act
__global__ __launch_bounds__(128) void edgeA_kernel(
    const float* __restrict__ radial,
    const float* __restrict__ w1, const float* __restrict__ w2,
    const float* __restrict__ w3)
{
    extern __shared__ float smem[];
    float* s1 = smem;               // 8*64   = 512
    float* s2 = s1 + 512;           // 64*64  = 4096
    float* s3 = s2 + 4096;          // 64*64  = 4096   (8704 floats = 34816 B)
    {
        float4* d; const float4* s;
        d = (float4*)s1; s = (const float4*)w1;
        for (int i = threadIdx.x; i < 128;  i += 128) d[i] = s[i];
        d = (float4*)s2; s = (const float4*)w2;
        for (int i = threadIdx.x; i < 1024; i += 128) d[i] = s[i];
        d = (float4*)s3; s = (const float4*)w3;
        for (int i = threadIdx.x; i < 1024; i += 128) d[i] = s[i];
    }
    __syncthreads();

    const int e = blockIdx.x * 128 + threadIdx.x;

    const float4* rr = (const float4*)(radial + e*8);
    float4 r0 = rr[0], r1 = rr[1];
    float rv[8] = {r0.x, r0.y, r0.z, r0.w, r1.x, r1.y, r1.z, r1.w};

    float a[64];
    // L1
    {
        ull q[32];
        #pragma unroll
        for (int p = 0; p < 32; p++) q[p] = 0ull;
        #pragma unroll
        for (int i = 0; i < 8; i++) {
            ull a2 = pack2(rv[i]);
            const ulonglong2* wr = (const ulonglong2*)(s1 + i*64);
            #pragma unroll
            for (int t = 0; t < 16; t++) {
                ulonglong2 wp = wr[t];
                ffma2(q[2*t],   wp.x, a2);
                ffma2(q[2*t+1], wp.y, a2);
            }
        }
        #pragma unroll
        for (int p = 0; p < 32; p++) {
            float2 f = unpk(q[p]);
            a[2*p]   = silu(f.x * 0.35355339059f);
            a[2*p+1] = silu(f.y * 0.35355339059f);
        }
    }
    layer64(s2, a, 0.125f);   // L2
    layer64(s3, a, 0.125f);   // L3

    float4* dst = (float4*)(g_act + (size_t)e*64);
    #pragma unroll
    for (int k = 0; k < 16; k++)
        dst[k] = make_float4(a[4*k], a[4*k+1], a[4*k+2], a[4*k+3]);
}

// ---------------------------------------------------------------- L4 pass: 8 channels (24 outputs) + scatter
__device__ __forceinline__ void l4pass8(const float* __restrict__ s4, const float a[64], int c0,
                                        const float4* __restrict__ hrow, float* __restrict__ aggb,
                                        const float y1v[3], const float y2v[5]) {
    const float KSC = 0.125f * (1.0f/64.0f);
    ull p0[4], p1[4], p2[4];
    #pragma unroll
    for (int k = 0; k < 4; k++) { p0[k] = 0ull; p1[k] = 0ull; p2[k] = 0ull; }
    #pragma unroll
    for (int i = 0; i < 64; i++) {
        ull a2 = pack2(a[i]);
        const ulonglong2* wa = (const ulonglong2*)(s4 + i*192 + c0);
        const ulonglong2* wb = (const ulonglong2*)(s4 + i*192 + 64 + c0);
        const ulonglong2* wc = (const ulonglong2*)(s4 + i*192 + 128 + c0);
        #pragma unroll
        for (int t = 0; t < 2; t++) {
            ulonglong2 w0 = wa[t]; ffma2(p0[2*t], w0.x, a2); ffma2(p0[2*t+1], w0.y, a2);
            ulonglong2 w1 = wb[t]; ffma2(p1[2*t], w1.x, a2); ffma2(p1[2*t+1], w1.y, a2);
            ulonglong2 w2 = wc[t]; ffma2(p2[2*t], w2.x, a2); ffma2(p2[2*t+1], w2.y, a2);
        }
    }
    #pragma unroll
    for (int k = 0; k < 2; k++) {
        float4 sv = hrow[(c0 >> 2) + k];
        float2 f0a = unpk(p0[2*k]), f0b = unpk(p0[2*k+1]);
        float2 f1a = unpk(p1[2*k]), f1b = unpk(p1[2*k+1]);
        float2 f2a = unpk(p2[2*k]), f2b = unpk(p2[2*k+1]);
        float t0[4] = { sv.x*f0a.x*KSC, sv.y*f0a.y*KSC, sv.z*f0b.x*KSC, sv.w*f0b.y*KSC };
        float t1[4] = { sv.x*f1a.x*KSC, sv.y*f1a.y*KSC, sv.z*f1b.x*KSC, sv.w*f1b.y*KSC };
        float t2[4] = { sv.x*f2a.x*KSC, sv.y*f2a.y*KSC, sv.z*f2b.x*KSC, sv.w*f2b.y*KSC };
        float* base = aggb + c0 + 4*k;
        red4(base, t0[0], t0[1], t0[2], t0[3]);
        #pragma unroll
        for (int m = 0; m < 3; m++) {
            float ym = y1v[m];
            red4(base + (1+m)*PL, t1[0]*ym, t1[1]*ym, t1[2]*ym, t1[3]*ym);
        }
        #pragma unroll
        for (int m = 0; m < 5; m++) {
            float ym = y2v[m];
            red4(base + (4+m)*PL, t2[0]*ym, t2[1]*ym, t2[2]*ym, t2[3]*ym);
        }
    }
}

// ---------------------------------------------------------------- edge B: L4 + SH + scatter
__global__ __launch_bounds__(128) void edgeB_kernel(
    const float* __restrict__ vectors,
    const int* __restrict__ senders, const int* __restrict__ receivers,
    const float* __restrict__ w4)
{
    extern __shared__ float s4[];   // 64*192 = 12288 floats = 49152 B
    {
        float4* d = (float4*)s4; const float4* s = (const float4*)w4;
        for (int i = threadIdx.x; i < 3072; i += 128) d[i] = s[i];
    }
    __syncthreads();

    const int e = blockIdx.x * 128 + threadIdx.x;

    float a[64];
    {
        const float4* src = (const float4*)(g_act + (size_t)e*64);
        #pragma unroll
        for (int k = 0; k < 16; k++) {
            float4 v = src[k];
            a[4*k] = v.x; a[4*k+1] = v.y; a[4*k+2] = v.z; a[4*k+3] = v.w;
        }
    }

    float vx = vectors[e*3], vy = vectors[e*3+1], vz = vectors[e*3+2];
    float inv = rsqrtf(vx*vx + vy*vy + vz*vz);
    float ux = vx*inv, uy = vy*inv, uz = vz*inv;
    const float SQ3 = 1.7320508075688772f, S15 = 3.872983346207417f;
    const float HS5 = 1.118033988749895f;
    float y1v[3] = {SQ3*ux, SQ3*uy, SQ3*uz};
    float y2v[5] = {S15*ux*uy, S15*uy*uz, HS5*(3.f*uz*uz - 1.f),
                    S15*ux*uz, 0.5f*S15*(ux*ux - uy*uy)};

    const int snd = senders[e], rcv = receivers[e];
    const float4* hrow = (const float4*)(g_h + snd*64);
    float* aggb = g_agg + rcv*64;

    #pragma unroll 1
    for (int c0 = 0; c0 < 64; c0 += 8)
        l4pass8(s4, a, c0, hrow, aggb, y1v, y2v);
}

// ---------------------------------------------------------------- down projection
// warp = 32 nodes (lane=node), 3 planes per warp; weights broadcast from shared; f32x2.
__global__ __launch_bounds__(256) void down_kernel(const float* __restrict__ w0, const float* __restrict__ w1,
                                                   const float* __restrict__ w2, float* __restrict__ out)
{
    extern __shared__ float sw[];   // 3*4096 = 12288 floats = 49152 B
    {
        float4* d = (float4*)sw;
        const float4* a4 = (const float4*)w0;
        const float4* b4 = (const float4*)w1;
        const float4* c4 = (const float4*)w2;
        for (int i = threadIdx.x; i < 1024; i += 256) {
            d[i]        = a4[i];
            d[1024 + i] = b4[i];
            d[2048 + i] = c4[i];
        }
    }
    __syncthreads();

    const int gw = blockIdx.x * 8 + (threadIdx.x >> 5);
    if (gw >= 1875) return;            // 625 node-groups x 3 plane-groups
    const int lane = threadIdx.x & 31;
    const int grp = gw / 3;            // node group
    const int pg  = gw - grp*3;        // plane group: planes pg*3 .. pg*3+2
    const int n = grp*32 + lane;
    const float S = 0.0625f;           // EPS(0.5) * inv_sqrt_c(0.125)
    float* ob = out + (size_t)n*576;

    #pragma unroll 1
    for (int pp = 0; pp < 3; pp++) {
        const int p = pg*3 + pp;
        const float* wsel = sw + (p == 0 ? 0 : (p < 4 ? 4096 : 8192));
        const float4* ar = (const float4*)(g_agg + (size_t)p*PL + (size_t)n*64);

        ull acc[32];
        #pragma unroll
        for (int k = 0; k < 32; k++) acc[k] = 0ull;

        #pragma unroll
        for (int c4i = 0; c4i < 16; c4i++) {
            float4 av = ar[c4i];
            float avf[4] = {av.x, av.y, av.z, av.w};
            #pragma unroll
            for (int j = 0; j < 4; j++) {
                ull a2 = pack2(avf[j]);
                const ulonglong2* wr = (const ulonglong2*)(wsel + (4*c4i + j)*64);
                #pragma unroll
                for (int t = 0; t < 16; t++) {
                    ulonglong2 wp = wr[t];
                    ffma2(acc[2*t],   wp.x, a2);
                    ffma2(acc[2*t+1], wp.y, a2);
                }
            }
        }

        if (p == 0) {
            float4* o4 = (float4*)ob;
            #pragma unroll
            for (int k = 0; k < 16; k++) {
                float2 lo = unpk(acc[2*k]), hi = unpk(acc[2*k+1]);
                o4[k] = make_float4(lo.x*S, lo.y*S, hi.x*S, hi.y*S);
            }
        } else if (p < 4) {
            float* b = ob + 64 + (p - 1);
            #pragma unroll
            for (int k = 0; k < 32; k++) {
                float2 f = unpk(acc[k]);
                b[3*(2*k)]   = f.x * S;
                b[3*(2*k+1)] = f.y * S;
            }
        } else {
            float* b = ob + 256 + (p - 4);
            #pragma unroll
            for (int k = 0; k < 32; k++) {
                float2 f = unpk(acc[k]);
                b[5*(2*k)]   = f.x * S;
                b[5*(2*k+1)] = f.y * S;
            }
        }
    }
}

// ---------------------------------------------------------------- launch
extern "C" void kernel_launch(void* const* d_in, const int* in_sizes, int n_in,
                              void* d_out, int out_size)
{
    const float* vectors    = (const float*)d_in[0];
    const float* node_feats = (const float*)d_in[1];
    const float* radial     = (const float*)d_in[2];
    const int*   senders    = (const int*)  d_in[3];
    const int*   receivers  = (const int*)  d_in[4];
    const float* w_up       = (const float*)d_in[5];
    const float* mlp_w1     = (const float*)d_in[6];
    const float* mlp_w2     = (const float*)d_in[7];
    const float* mlp_w3     = (const float*)d_in[8];
    const float* mlp_w4     = (const float*)d_in[9];
    const float* w_down0    = (const float*)d_in[10];
    const float* w_down1    = (const float*)d_in[11];
    const float* w_down2    = (const float*)d_in[12];
    float* out = (float*)d_out;

    const int A_SMEM = 8704 * 4;    // 34816 B
    const int B_SMEM = 12288 * 4;   // 49152 B
    const int D_SMEM = 12288 * 4;   // 49152 B
    cudaFuncSetAttribute(edgeA_kernel, cudaFuncAttributeMaxDynamicSharedMemorySize, A_SMEM);
    cudaFuncSetAttribute(edgeB_kernel, cudaFuncAttributeMaxDynamicSharedMemorySize, B_SMEM);
    cudaFuncSetAttribute(down_kernel,  cudaFuncAttributeMaxDynamicSharedMemorySize, D_SMEM);

    void* aggp = nullptr;
    cudaGetSymbolAddress(&aggp, g_agg);
    cudaMemsetAsync(aggp, 0, (size_t)9 * PL * sizeof(float));

    up_kernel<<<NN/4, 256>>>(node_feats, w_up);
    edgeA_kernel<<<NE/128, 128, A_SMEM>>>(radial, mlp_w1, mlp_w2, mlp_w3);
    edgeB_kernel<<<NE/128, 128, B_SMEM>>>(vectors, senders, receivers, mlp_w4);
    down_kernel<<<(1875 + 7)/8, 256, D_SMEM>>>(w_down0, w_down1, w_down2, out);
}

// round 4
// speedup vs baseline: 2.4329x; 1.0084x over previous
#include <cuda_runtime.h>

#define NN 20000
#define NE 320000
#define CC 64
#define PL (NN*CC)          // one plane of agg: [NN, 64]

typedef unsigned long long ull;

// Scratch (allocation-free rule: __device__ globals)
__device__ __align__(16) float g_h[NN*CC];        // 5.1 MB
__device__ __align__(16) float g_agg[9*PL];       // 46 MB, 9 planes
__device__ __align__(16) float g_act[NE*CC];      // 82 MB, edge MLP activations
__device__ __align__(16) float g_msg[(size_t)NE*192]; // 246 MB, per-edge t0|t1|t2
__device__ __align__(16) float g_y[NE*8];         // 10 MB, per-edge SH values
__device__ int g_cnt[NN];
__device__ int g_off[NN+1];
__device__ int g_cur[NN];
__device__ int g_order[NE];

__device__ __forceinline__ float silu(float x) {
    return x * (1.0f / (1.0f + __expf(-x)));
}
__device__ __forceinline__ ull pack2(float x) {
    ull r; asm("mov.b64 %0, {%1, %1};" : "=l"(r) : "f"(x)); return r;
}
__device__ __forceinline__ void ffma2(ull& q, ull w, ull a) {
    asm("fma.rn.f32x2 %0, %1, %2, %0;" : "+l"(q) : "l"(w), "l"(a));
}
__device__ __forceinline__ float2 unpk(ull v) {
    float lo, hi; asm("mov.b64 {%0, %1}, %2;" : "=f"(lo), "=f"(hi) : "l"(v));
    return make_float2(lo, hi);
}

// ---------------------------------------------------------------- h = nf @ w_up * (1/8)
__global__ void up_kernel(const float* __restrict__ nf, const float* __restrict__ wup) {
    __shared__ float ws[CC*CC];
    __shared__ float rows[4*CC];
    for (int i = threadIdx.x; i < CC*CC; i += blockDim.x) ws[i] = wup[i];
    int base = blockIdx.x * 4 * CC;
    rows[threadIdx.x] = nf[base + threadIdx.x];
    __syncthreads();
    int r = threadIdx.x >> 6;
    int c = threadIdx.x & 63;
    float acc = 0.f;
    #pragma unroll
    for (int i = 0; i < CC; i++) acc = fmaf(rows[r*CC + i], ws[i*CC + c], acc);
    g_h[base + threadIdx.x] = acc * 0.125f;
}

// ---------------------------------------------------------------- 64->64 MLP layer, packed f32x2
__device__ __forceinline__ void layer64(const float* __restrict__ w, float a[64], float scale) {
    ull q[32];
    #pragma unroll
    for (int p = 0; p < 32; p++) q[p] = 0ull;
    #pragma unroll
    for (int i = 0; i < 64; i++) {
        ull a2 = pack2(a[i]);
        const ulonglong2* wr = (const ulonglong2*)(w + i*64);
        #pragma unroll
        for (int t = 0; t < 16; t++) {
            ulonglong2 wp = wr[t];
            ffma2(q[2*t],   wp.x, a2);
            ffma2(q[2*t+1], wp.y, a2);
        }
    }
    #pragma unroll
    for (int p = 0; p < 32; p++) {
        float2 f = unpk(q[p]);
        a[2*p]   = silu(f.x * scale);
        a[2*p+1] = silu(f.y * scale);
    }
}

// ---------------------------------------------------------------- edge A: radial MLP L1-L3 -> g_act
__global__ __launch_bounds__(128) void edgeA_kernel(
    const float* __restrict__ radial,
    const float* __restrict__ w1, const float* __restrict__ w2,
    const float* __restrict__ w3)
{
    extern __shared__ float smem[];
    float* s1 = smem;               // 8*64
    float* s2 = s1 + 512;           // 64*64
    float* s3 = s2 + 4096;          // 64*64
    {
        float4* d; const float4* s;
        d = (float4*)s1; s = (const float4*)w1;
        for (int i = threadIdx.x; i < 128;  i += 128) d[i] = s[i];
        d = (float4*)s2; s = (const float4*)w2;
        for (int i = threadIdx.x; i < 1024; i += 128) d[i] = s[i];
        d = (float4*)s3; s = (const float4*)w3;
        for (int i = threadIdx.x; i < 1024; i += 128) d[i] = s[i];
    }
    __syncthreads();

    const int e = blockIdx.x * 128 + threadIdx.x;

    const float4* rr = (const float4*)(radial + e*8);
    float4 r0 = rr[0], r1 = rr[1];
    float rv[8] = {r0.x, r0.y, r0.z, r0.w, r1.x, r1.y, r1.z, r1.w};

    float a[64];
    {
        ull q[32];
        #pragma unroll
        for (int p = 0; p < 32; p++) q[p] = 0ull;
        #pragma unroll
        for (int i = 0; i < 8; i++) {
            ull a2 = pack2(rv[i]);
            const ulonglong2* wr = (const ulonglong2*)(s1 + i*64);
            #pragma unroll
            for (int t = 0; t < 16; t++) {
                ulonglong2 wp = wr[t];
                ffma2(q[2*t],   wp.x, a2);
                ffma2(q[2*t+1], wp.y, a2);
            }
        }
        #pragma unroll
        for (int p = 0; p < 32; p++) {
            float2 f = unpk(q[p]);
            a[2*p]   = silu(f.x * 0.35355339059f);
            a[2*p+1] = silu(f.y * 0.35355339059f);
        }
    }
    layer64(s2, a, 0.125f);   // L2
    layer64(s3, a, 0.125f);   // L3

    float4* dst = (float4*)(g_act + (size_t)e*64);
    #pragma unroll
    for (int k = 0; k < 16; k++)
        dst[k] = make_float4(a[4*k], a[4*k+1], a[4*k+2], a[4*k+3]);
}

// ---------------------------------------------------------------- edge B: L4 -> g_msg, SH -> g_y (no atomics)
__global__ __launch_bounds__(128) void edgeB_kernel(
    const float* __restrict__ vectors,
    const int* __restrict__ senders,
    const float* __restrict__ w4)
{
    extern __shared__ float s4[];   // 64*192 floats = 48 KB
    {
        float4* d = (float4*)s4; const float4* s = (const float4*)w4;
        for (int i = threadIdx.x; i < 3072; i += 128) d[i] = s[i];
    }
    __syncthreads();

    const int e = blockIdx.x * 128 + threadIdx.x;

    float a[64];
    {
        const float4* src = (const float4*)(g_act + (size_t)e*64);
        #pragma unroll
        for (int k = 0; k < 16; k++) {
            float4 v = src[k];
            a[4*k] = v.x; a[4*k+1] = v.y; a[4*k+2] = v.z; a[4*k+3] = v.w;
        }
    }

    // spherical harmonics -> g_y
    {
        float vx = vectors[e*3], vy = vectors[e*3+1], vz = vectors[e*3+2];
        float inv = rsqrtf(vx*vx + vy*vy + vz*vz);
        float ux = vx*inv, uy = vy*inv, uz = vz*inv;
        const float SQ3 = 1.7320508075688772f, S15 = 3.872983346207417f;
        const float HS5 = 1.118033988749895f;
        float4* yp = (float4*)(g_y + e*8);
        yp[0] = make_float4(SQ3*ux, SQ3*uy, SQ3*uz, S15*ux*uy);
        yp[1] = make_float4(S15*uy*uz, HS5*(3.f*uz*uz - 1.f), S15*ux*uz, 0.5f*S15*(ux*ux - uy*uy));
    }

    const int snd = senders[e];
    const float4* hrow = (const float4*)(g_h + snd*64);
    float* mb = g_msg + (size_t)e*192;
    const float KSC = 0.125f * (1.0f/64.0f);

    #pragma unroll 1
    for (int c0 = 0; c0 < 64; c0 += 8) {
        ull p0[4], p1[4], p2[4];
        #pragma unroll
        for (int k = 0; k < 4; k++) { p0[k] = 0ull; p1[k] = 0ull; p2[k] = 0ull; }
        #pragma unroll
        for (int i = 0; i < 64; i++) {
            ull a2 = pack2(a[i]);
            const ulonglong2* wa = (const ulonglong2*)(s4 + i*192 + c0);
            const ulonglong2* wb = (const ulonglong2*)(s4 + i*192 + 64 + c0);
            const ulonglong2* wc = (const ulonglong2*)(s4 + i*192 + 128 + c0);
            #pragma unroll
            for (int t = 0; t < 2; t++) {
                ulonglong2 w0 = wa[t]; ffma2(p0[2*t], w0.x, a2); ffma2(p0[2*t+1], w0.y, a2);
                ulonglong2 w1 = wb[t]; ffma2(p1[2*t], w1.x, a2); ffma2(p1[2*t+1], w1.y, a2);
                ulonglong2 w2 = wc[t]; ffma2(p2[2*t], w2.x, a2); ffma2(p2[2*t+1], w2.y, a2);
            }
        }
        #pragma unroll
        for (int k = 0; k < 2; k++) {
            float4 sv = hrow[(c0 >> 2) + k];
            float2 f0a = unpk(p0[2*k]), f0b = unpk(p0[2*k+1]);
            float2 f1a = unpk(p1[2*k]), f1b = unpk(p1[2*k+1]);
            float2 f2a = unpk(p2[2*k]), f2b = unpk(p2[2*k+1]);
            *(float4*)(mb + c0 + 4*k)       = make_float4(sv.x*f0a.x*KSC, sv.y*f0a.y*KSC, sv.z*f0b.x*KSC, sv.w*f0b.y*KSC);
            *(float4*)(mb + 64 + c0 + 4*k)  = make_float4(sv.x*f1a.x*KSC, sv.y*f1a.y*KSC, sv.z*f1b.x*KSC, sv.w*f1b.y*KSC);
            *(float4*)(mb + 128 + c0 + 4*k) = make_float4(sv.x*f2a.x*KSC, sv.y*f2a.y*KSC, sv.z*f2b.x*KSC, sv.w*f2b.y*KSC);
        }
    }
}

// ---------------------------------------------------------------- counting sort by receiver
__global__ void hist_kernel(const int* __restrict__ receivers) {
    int e = blockIdx.x * blockDim.x + threadIdx.x;
    if (e < NE) atomicAdd(&g_cnt[receivers[e]], 1);
}

__global__ void scan_kernel() {   // single block, 1024 threads; 20 bins/thread
    __shared__ int part[1024];
    const int t = threadIdx.x;
    const int base = t * 20;
    int sum = 0;
    if (t < 1000) {
        #pragma unroll
        for (int k = 0; k < 20; k++) sum += g_cnt[base + k];
    }
    part[t] = sum;
    __syncthreads();
    #pragma unroll
    for (int off = 1; off < 1024; off <<= 1) {
        int v = (t >= off) ? part[t - off] : 0;
        __syncthreads();
        part[t] += v;
        __syncthreads();
    }
    if (t < 1000) {
        int run = part[t] - sum;   // exclusive base for this chunk
        #pragma unroll
        for (int k = 0; k < 20; k++) {
            g_off[base + k] = run;
            g_cur[base + k] = run;
            run += g_cnt[base + k];
        }
    }
    if (t == 0) g_off[NN] = NE;
}

__global__ void order_kernel(const int* __restrict__ receivers) {
    int e = blockIdx.x * blockDim.x + threadIdx.x;
    if (e < NE) {
        int pos = atomicAdd(&g_cur[receivers[e]], 1);
        g_order[pos] = e;
    }
}

// ---------------------------------------------------------------- gather: warp per node, no atomics
__global__ __launch_bounds__(128) void gather_kernel() {
    const int n = (blockIdx.x * 128 + threadIdx.x) >> 5;
    if (n >= NN) return;
    const int lane = threadIdx.x & 31;
    const int c0 = lane * 2;

    const int s = g_off[n], epos = g_off[n+1];

    float a0x=0.f, a0y=0.f;
    float a1x[3]={0,0,0}, a1y[3]={0,0,0};
    float a2x[5]={0,0,0,0,0}, a2y[5]={0,0,0,0,0};

    for (int i = s; i < epos; i++) {
        int e = g_order[i];
        const float* mp = g_msg + (size_t)e*192;
        float2 t0 = *(const float2*)(mp + c0);
        float2 t1 = *(const float2*)(mp + 64 + c0);
        float2 t2 = *(const float2*)(mp + 128 + c0);
        const float4* yp = (const float4*)(g_y + e*8);
        float4 ya = yp[0], yb = yp[1];
        float y1v[3] = {ya.x, ya.y, ya.z};
        float y2v[5] = {ya.w, yb.x, yb.y, yb.z, yb.w};
        a0x += t0.x; a0y += t0.y;
        #pragma unroll
        for (int m = 0; m < 3; m++) { a1x[m] = fmaf(t1.x, y1v[m], a1x[m]); a1y[m] = fmaf(t1.y, y1v[m], a1y[m]); }
        #pragma unroll
        for (int m = 0; m < 5; m++) { a2x[m] = fmaf(t2.x, y2v[m], a2x[m]); a2y[m] = fmaf(t2.y, y2v[m], a2y[m]); }
    }

    float* row = g_agg + (size_t)n*64 + c0;
    *(float2*)row = make_float2(a0x, a0y);
    #pragma unroll
    for (int m = 0; m < 3; m++)
        *(float2*)(row + (size_t)(1+m)*PL) = make_float2(a1x[m], a1y[m]);
    #pragma unroll
    for (int m = 0; m < 5; m++)
        *(float2*)(row + (size_t)(4+m)*PL) = make_float2(a2x[m], a2y[m]);
}

// ---------------------------------------------------------------- down projection v3
// grid = 9 planes x 79; block = 8 warps; warp = (plane, 32 nodes); weights 16KB smem; staged a-tile.
#define DGRP 79
__global__ __launch_bounds__(256) void down_kernel(const float* __restrict__ w0, const float* __restrict__ w1,
                                                   const float* __restrict__ w2, float* __restrict__ out)
{
    extern __shared__ float sm[];
    float* swp   = sm;            // 4096 floats (16 KB)
    float* tiles = sm + 4096;     // 8 * 32*65 floats

    const int plane = blockIdx.x / DGRP;
    const float* wsrc = (plane == 0) ? w0 : (plane < 4 ? w1 : w2);
    {
        float4* d = (float4*)swp; const float4* s = (const float4*)wsrc;
        for (int i = threadIdx.x; i < 1024; i += 256) d[i] = s[i];
    }
    __syncthreads();

    const int wid = threadIdx.x >> 5, lane = threadIdx.x & 31;
    const int grp = (blockIdx.x % DGRP) * 8 + wid;
    if (grp >= 625) return;
    const int n0 = grp * 32;

    float* tile = tiles + wid * (32*65);
    {   // coalesced stage of agg[plane][n0..n0+32][0..64] into padded tile
        const float4* src = (const float4*)(g_agg + (size_t)plane*PL + (size_t)n0*64);
        #pragma unroll
        for (int j = 0; j < 16; j++) {
            int idx = j*32 + lane;
            float4 v = src[idx];
            float* tp = tile + (idx >> 4)*65 + (idx & 15)*4;
            tp[0] = v.x; tp[1] = v.y; tp[2] = v.z; tp[3] = v.w;
        }
    }
    __syncwarp();

    const float* arow = tile + lane*65;
    ull acc[32];
    #pragma unroll
    for (int k = 0; k < 32; k++) acc[k] = 0ull;
    #pragma unroll
    for (int c = 0; c < 64; c++) {
        ull a2 = pack2(arow[c]);
        const ulonglong2* wr = (const ulonglong2*)(swp + c*64);
        #pragma unroll
        for (int t = 0; t < 16; t++) {
            ulonglong2 wp = wr[t];
            ffma2(acc[2*t],   wp.x, a2);
            ffma2(acc[2*t+1], wp.y, a2);
        }
    }

    const float S = 0.0625f;  // EPS(0.5) * inv_sqrt_c(0.125)
    const int n = n0 + lane;
    float* ob = out + (size_t)n*576;
    if (plane == 0) {
        float4* o4 = (float4*)ob;
        #pragma unroll
        for (int k = 0; k < 16; k++) {
            float2 lo = unpk(acc[2*k]), hi = unpk(acc[2*k+1]);
            o4[k] = make_float4(lo.x*S, lo.y*S, hi.x*S, hi.y*S);
        }
    } else if (plane < 4) {
        float* b = ob + 64 + (plane - 1);
        #pragma unroll
        for (int k = 0; k < 32; k++) {
            float2 f = unpk(acc[k]);
            b[3*(2*k)]   = f.x * S;
            b[3*(2*k+1)] = f.y * S;
        }
    } else {
        float* b = ob + 256 + (plane - 4);
        #pragma unroll
        for (int k = 0; k < 32; k++) {
            float2 f = unpk(acc[k]);
            b[5*(2*k)]   = f.x * S;
            b[5*(2*k+1)] = f.y * S;
        }
    }
}

// ---------------------------------------------------------------- launch
extern "C" void kernel_launch(void* const* d_in, const int* in_sizes, int n_in,
                              void* d_out, int out_size)
{
    const float* vectors    = (const float*)d_in[0];
    const float* node_feats = (const float*)d_in[1];
    const float* radial     = (const float*)d_in[2];
    const int*   senders    = (const int*)  d_in[3];
    const int*   receivers  = (const int*)  d_in[4];
    const float* w_up       = (const float*)d_in[5];
    const float* mlp_w1     = (const float*)d_in[6];
    const float* mlp_w2     = (const float*)d_in[7];
    const float* mlp_w3     = (const float*)d_in[8];
    const float* mlp_w4     = (const float*)d_in[9];
    const float* w_down0    = (const float*)d_in[10];
    const float* w_down1    = (const float*)d_in[11];
    const float* w_down2    = (const float*)d_in[12];
    float* out = (float*)d_out;

    const int A_SMEM = 8704 * 4;                 // 34816 B
    const int B_SMEM = 12288 * 4;                // 49152 B
    const int D_SMEM = (4096 + 8*32*65) * 4;     // 82944 B
    cudaFuncSetAttribute(edgeA_kernel, cudaFuncAttributeMaxDynamicSharedMemorySize, A_SMEM);
    cudaFuncSetAttribute(edgeB_kernel, cudaFuncAttributeMaxDynamicSharedMemorySize, B_SMEM);
    cudaFuncSetAttribute(down_kernel,  cudaFuncAttributeMaxDynamicSharedMemorySize, D_SMEM);

    void* cntp = nullptr;
    cudaGetSymbolAddress(&cntp, g_cnt);
    cudaMemsetAsync(cntp, 0, NN * sizeof(int));

    up_kernel<<<NN/4, 256>>>(node_feats, w_up);
    hist_kernel<<<(NE + 255)/256, 256>>>(receivers);
    scan_kernel<<<1, 1024>>>();
    order_kernel<<<(NE + 255)/256, 256>>>(receivers);
    edgeA_kernel<<<NE/128, 128, A_SMEM>>>(radial, mlp_w1, mlp_w2, mlp_w3);
    edgeB_kernel<<<NE/128, 128, B_SMEM>>>(vectors, senders, mlp_w4);
    gather_kernel<<<(NN*32 + 127)/128, 128>>>();
    down_kernel<<<9*DGRP, 256, D_SMEM>>>(w_down0, w_down1, w_down2, out);
}

// round 6
// speedup vs baseline: 4.6045x; 1.8926x over previous
#include <cuda_runtime.h>
#include <cuda_bf16.h>
#include <cstdint>

#define NN 20000
#define NE 320000
#define CC 64
#define PL (NN*CC)

typedef unsigned long long ull;

// Scratch (allocation-free rule: __device__ globals)
__device__ __align__(16) float g_h[NN*CC];            // 5.1 MB
__device__ __align__(16) float g_agg[9*PL];           // 46 MB
__device__ __align__(16) float g_msg[(size_t)NE*192]; // 246 MB
__device__ __align__(16) float g_y[NE*8];             // 10 MB
__device__ __align__(16) uint4 g_wfrag[168*32];       // 86 KB packed B fragments
__device__ int g_cnt[NN];
__device__ int g_off[NN+1];
__device__ int g_cur[NN];
__device__ int g_order[NE];

__device__ __forceinline__ float silu(float x) {
    return x * (1.0f / (1.0f + __expf(-x)));
}
__device__ __forceinline__ ull pack2(float x) {
    ull r; asm("mov.b64 %0, {%1, %1};" : "=l"(r) : "f"(x)); return r;
}
__device__ __forceinline__ void ffma2(ull& q, ull w, ull a) {
    asm("fma.rn.f32x2 %0, %1, %2, %0;" : "+l"(q) : "l"(w), "l"(a));
}
__device__ __forceinline__ float2 unpk(ull v) {
    float lo, hi; asm("mov.b64 {%0, %1}, %2;" : "=f"(lo), "=f"(hi) : "l"(v));
    return make_float2(lo, hi);
}

// pack (x0 -> low half, x1 -> high half) as bf16x2; return hi-word, write lo(residual)-word
__device__ __forceinline__ uint32_t split_pair(float x0, float x1, uint32_t& lw) {
    uint32_t hw;
    asm("cvt.rn.bf16x2.f32 %0, %1, %2;" : "=r"(hw) : "f"(x1), "f"(x0));
    float h0 = __uint_as_float(hw << 16);
    float h1 = __uint_as_float(hw & 0xffff0000u);
    asm("cvt.rn.bf16x2.f32 %0, %1, %2;" : "=r"(lw) : "f"(x1 - h1), "f"(x0 - h0));
    return hw;
}

__device__ __forceinline__ void mma16816(float c[4],
    uint32_t a0, uint32_t a1, uint32_t a2, uint32_t a3, uint32_t b0, uint32_t b1)
{
    asm volatile("mma.sync.aligned.m16n8k16.row.col.f32.bf16.bf16.f32 "
        "{%0,%1,%2,%3},{%4,%5,%6,%7},{%8,%9},{%0,%1,%2,%3};"
        : "+f"(c[0]), "+f"(c[1]), "+f"(c[2]), "+f"(c[3])
        : "r"(a0), "r"(a1), "r"(a2), "r"(a3), "r"(b0), "r"(b1));
}

// ---------------------------------------------------------------- prep: pack B fragments
// tile map: [0,8) L1 (kt=0) ; [8,40) L2 ; [40,72) L3 ; [72,168) L4 (kt*24+nt)
__global__ void prep_kernel(const float* __restrict__ w1, const float* __restrict__ w2,
                            const float* __restrict__ w3, const float* __restrict__ w4)
{
    const int tile = blockIdx.x;
    const int lane = threadIdx.x;
    const int g = lane >> 2, tig = lane & 3;
    const float* W; int K, Nc, kt, nt; float sc;
    if (tile < 8)        { W = w1; K = 8;  Nc = 64;  kt = 0;            nt = tile;          sc = 0.35355339059f; }
    else if (tile < 40)  { int t = tile-8;  W = w2; K = 64; Nc = 64;  kt = t >> 3;       nt = t & 7;          sc = 0.125f; }
    else if (tile < 72)  { int t = tile-40; W = w3; K = 64; Nc = 64;  kt = t >> 3;       nt = t & 7;          sc = 0.125f; }
    else                 { int t = tile-72; W = w4; K = 64; Nc = 192; kt = t / 24;       nt = t % 24;         sc = 0.001953125f; }
    const int n = nt*8 + g;
    const int k0 = kt*16 + 2*tig;
    float x00 = (k0   < K) ? W[(k0  )*Nc + n]*sc : 0.f;
    float x01 = (k0+1 < K) ? W[(k0+1)*Nc + n]*sc : 0.f;
    float x10 = (k0+8 < K) ? W[(k0+8)*Nc + n]*sc : 0.f;
    float x11 = (k0+9 < K) ? W[(k0+9)*Nc + n]*sc : 0.f;
    uint32_t l0, l1;
    uint32_t h0 = split_pair(x00, x01, l0);
    uint32_t h1 = split_pair(x10, x11, l1);
    g_wfrag[tile*32 + lane] = make_uint4(h0, h1, l0, l1);
}

// ---------------------------------------------------------------- h = nf @ w_up * (1/8)
__global__ void up_kernel(const float* __restrict__ nf, const float* __restrict__ wup) {
    __shared__ float ws[CC*CC];
    __shared__ float rows[4*CC];
    for (int i = threadIdx.x; i < CC*CC; i += blockDim.x) ws[i] = wup[i];
    int base = blockIdx.x * 4 * CC;
    rows[threadIdx.x] = nf[base + threadIdx.x];
    __syncthreads();
    int r = threadIdx.x >> 6;
    int c = threadIdx.x & 63;
    float acc = 0.f;
    #pragma unroll
    for (int i = 0; i < CC; i++) acc = fmaf(rows[r*CC + i], ws[i*CC + c], acc);
    g_h[base + threadIdx.x] = acc * 0.125f;
}

// ---------------------------------------------------------------- edgeM: full MLP on mma.sync bf16
__device__ __forceinline__ void layerK64(int tbase, int lane, float C[8][4],
                                         const uint32_t Ah[4][4], const uint32_t Al[4][4])
{
    #pragma unroll
    for (int nt = 0; nt < 8; nt++) {
        C[nt][0] = C[nt][1] = C[nt][2] = C[nt][3] = 0.f;
        #pragma unroll
        for (int kt = 0; kt < 4; kt++) {
            uint4 wf = g_wfrag[(tbase + kt*8 + nt)*32 + lane];
            mma16816(C[nt], Ah[kt][0], Ah[kt][1], Ah[kt][2], Ah[kt][3], wf.x, wf.y);
            mma16816(C[nt], Ah[kt][0], Ah[kt][1], Ah[kt][2], Ah[kt][3], wf.z, wf.w);
            mma16816(C[nt], Al[kt][0], Al[kt][1], Al[kt][2], Al[kt][3], wf.x, wf.y);
        }
    }
}

__device__ __forceinline__ void transition(const float C[8][4], uint32_t Ah[4][4], uint32_t Al[4][4])
{
    #pragma unroll
    for (int kt = 0; kt < 4; kt++) {
        const float* ca = C[2*kt];
        const float* cb = C[2*kt+1];
        Ah[kt][0] = split_pair(silu(ca[0]), silu(ca[1]), Al[kt][0]);
        Ah[kt][1] = split_pair(silu(ca[2]), silu(ca[3]), Al[kt][1]);
        Ah[kt][2] = split_pair(silu(cb[0]), silu(cb[1]), Al[kt][2]);
        Ah[kt][3] = split_pair(silu(cb[2]), silu(cb[3]), Al[kt][3]);
    }
}

__global__ __launch_bounds__(128) void edgeM_kernel(
    const float* __restrict__ vectors, const float* __restrict__ radial,
    const int* __restrict__ senders)
{
    const int wt = blockIdx.x*4 + (threadIdx.x >> 5);   // 0..19999, 16 edges each
    const int lane = threadIdx.x & 31;
    const int g = lane >> 2, tig = lane & 3;
    const int base = wt*16;
    const int e0 = base + g, e1 = e0 + 8;

    uint32_t Ah[4][4], Al[4][4];
    // L1 A fragments from radial (K=8, zero-padded to 16)
    {
        float2 r0 = *(const float2*)(radial + (size_t)e0*8 + 2*tig);
        float2 r1 = *(const float2*)(radial + (size_t)e1*8 + 2*tig);
        Ah[0][0] = split_pair(r0.x, r0.y, Al[0][0]);
        Ah[0][1] = split_pair(r1.x, r1.y, Al[0][1]);
        Ah[0][2] = 0; Ah[0][3] = 0; Al[0][2] = 0; Al[0][3] = 0;
    }

    float C[8][4];
    // ---- L1 (kt = 0 only, tiles 0..7) ----
    #pragma unroll
    for (int nt = 0; nt < 8; nt++) {
        C[nt][0] = C[nt][1] = C[nt][2] = C[nt][3] = 0.f;
        uint4 wf = g_wfrag[nt*32 + lane];
        mma16816(C[nt], Ah[0][0], Ah[0][1], Ah[0][2], Ah[0][3], wf.x, wf.y);
        mma16816(C[nt], Ah[0][0], Ah[0][1], Ah[0][2], Ah[0][3], wf.z, wf.w);
        mma16816(C[nt], Al[0][0], Al[0][1], Al[0][2], Al[0][3], wf.x, wf.y);
    }
    transition(C, Ah, Al);
    layerK64(8, lane, C, Ah, Al);    // L2
    transition(C, Ah, Al);
    layerK64(40, lane, C, Ah, Al);   // L3
    transition(C, Ah, Al);

    // ---- L4 (N=192 in 3 plane-chunks) + epilogue ----
    const int snd0 = senders[e0], snd1 = senders[e1];
    const float* h0r = g_h + (size_t)snd0*64;
    const float* h1r = g_h + (size_t)snd1*64;
    float* m0 = g_msg + (size_t)e0*192;
    float* m1 = g_msg + (size_t)e1*192;

    #pragma unroll
    for (int p = 0; p < 3; p++) {
        float D[8][4];
        #pragma unroll
        for (int ntl = 0; ntl < 8; ntl++) {
            D[ntl][0] = D[ntl][1] = D[ntl][2] = D[ntl][3] = 0.f;
            #pragma unroll
            for (int kt = 0; kt < 4; kt++) {
                uint4 wf = g_wfrag[(72 + kt*24 + p*8 + ntl)*32 + lane];
                mma16816(D[ntl], Ah[kt][0], Ah[kt][1], Ah[kt][2], Ah[kt][3], wf.x, wf.y);
                mma16816(D[ntl], Ah[kt][0], Ah[kt][1], Ah[kt][2], Ah[kt][3], wf.z, wf.w);
                mma16816(D[ntl], Al[kt][0], Al[kt][1], Al[kt][2], Al[kt][3], wf.x, wf.y);
            }
        }
        #pragma unroll
        for (int ntl = 0; ntl < 8; ntl++) {
            int col = 8*ntl + 2*tig;
            float2 h0 = *(const float2*)(h0r + col);
            float2 h1 = *(const float2*)(h1r + col);
            *(float2*)(m0 + p*64 + col) = make_float2(D[ntl][0]*h0.x, D[ntl][1]*h0.y);
            *(float2*)(m1 + p*64 + col) = make_float2(D[ntl][2]*h1.x, D[ntl][3]*h1.y);
        }
    }

    // spherical harmonics (lanes 0..15, one edge each)
    if (lane < 16) {
        const int e = base + lane;
        float vx = vectors[e*3], vy = vectors[e*3+1], vz = vectors[e*3+2];
        float inv = rsqrtf(vx*vx + vy*vy + vz*vz);
        float ux = vx*inv, uy = vy*inv, uz = vz*inv;
        const float SQ3 = 1.7320508075688772f, S15 = 3.872983346207417f;
        const float HS5 = 1.118033988749895f;
        float4* yp = (float4*)(g_y + (size_t)e*8);
        yp[0] = make_float4(SQ3*ux, SQ3*uy, SQ3*uz, S15*ux*uy);
        yp[1] = make_float4(S15*uy*uz, HS5*(3.f*uz*uz - 1.f), S15*ux*uz, 0.5f*S15*(ux*ux - uy*uy));
    }
}

// ---------------------------------------------------------------- counting sort by receiver
__global__ void hist_kernel(const int* __restrict__ receivers) {
    int e = blockIdx.x * blockDim.x + threadIdx.x;
    if (e < NE) atomicAdd(&g_cnt[receivers[e]], 1);
}

__global__ void scan_kernel() {
    __shared__ int part[1024];
    const int t = threadIdx.x;
    const int base = t * 20;
    int sum = 0;
    if (t < 1000) {
        #pragma unroll
        for (int k = 0; k < 20; k++) sum += g_cnt[base + k];
    }
    part[t] = sum;
    __syncthreads();
    #pragma unroll
    for (int off = 1; off < 1024; off <<= 1) {
        int v = (t >= off) ? part[t - off] : 0;
        __syncthreads();
        part[t] += v;
        __syncthreads();
    }
    if (t < 1000) {
        int run = part[t] - sum;
        #pragma unroll
        for (int k = 0; k < 20; k++) {
            g_off[base + k] = run;
            g_cur[base + k] = run;
            run += g_cnt[base + k];
        }
    }
    if (t == 0) g_off[NN] = NE;
}

__global__ void order_kernel(const int* __restrict__ receivers) {
    int e = blockIdx.x * blockDim.x + threadIdx.x;
    if (e < NE) {
        int pos = atomicAdd(&g_cur[receivers[e]], 1);
        g_order[pos] = e;
    }
}

// ---------------------------------------------------------------- gather: warp per node
__global__ __launch_bounds__(128) void gather_kernel() {
    const int n = (blockIdx.x * 128 + threadIdx.x) >> 5;
    if (n >= NN) return;
    const int lane = threadIdx.x & 31;
    const int c0 = lane * 2;

    const int s = g_off[n], epos = g_off[n+1];

    float a0x=0.f, a0y=0.f;
    float a1x[3]={0,0,0}, a1y[3]={0,0,0};
    float a2x[5]={0,0,0,0,0}, a2y[5]={0,0,0,0,0};

    for (int i = s; i < epos; i++) {
        int e = g_order[i];
        const float* mp = g_msg + (size_t)e*192;
        float2 t0 = *(const float2*)(mp + c0);
        float2 t1 = *(const float2*)(mp + 64 + c0);
        float2 t2 = *(const float2*)(mp + 128 + c0);
        const float4* yp = (const float4*)(g_y + (size_t)e*8);
        float4 ya = yp[0], yb = yp[1];
        float y1v[3] = {ya.x, ya.y, ya.z};
        float y2v[5] = {ya.w, yb.x, yb.y, yb.z, yb.w};
        a0x += t0.x; a0y += t0.y;
        #pragma unroll
        for (int m = 0; m < 3; m++) { a1x[m] = fmaf(t1.x, y1v[m], a1x[m]); a1y[m] = fmaf(t1.y, y1v[m], a1y[m]); }
        #pragma unroll
        for (int m = 0; m < 5; m++) { a2x[m] = fmaf(t2.x, y2v[m], a2x[m]); a2y[m] = fmaf(t2.y, y2v[m], a2y[m]); }
    }

    float* row = g_agg + (size_t)n*64 + c0;
    *(float2*)row = make_float2(a0x, a0y);
    #pragma unroll
    for (int m = 0; m < 3; m++)
        *(float2*)(row + (size_t)(1+m)*PL) = make_float2(a1x[m], a1y[m]);
    #pragma unroll
    for (int m = 0; m < 5; m++)
        *(float2*)(row + (size_t)(4+m)*PL) = make_float2(a2x[m], a2y[m]);
}

// ---------------------------------------------------------------- down projection
#define DGRP 79
__global__ __launch_bounds__(256) void down_kernel(const float* __restrict__ w0, const float* __restrict__ w1,
                                                   const float* __restrict__ w2, float* __restrict__ out)
{
    extern __shared__ float sm[];
    float* swp   = sm;            // 4096 floats
    float* tiles = sm + 4096;     // 8 * 32*65 floats

    const int plane = blockIdx.x / DGRP;
    const float* wsrc = (plane == 0) ? w0 : (plane < 4 ? w1 : w2);
    {
        float4* d = (float4*)swp; const float4* s = (const float4*)wsrc;
        for (int i = threadIdx.x; i < 1024; i += 256) d[i] = s[i];
    }
    __syncthreads();

    const int wid = threadIdx.x >> 5, lane = threadIdx.x & 31;
    const int grp = (blockIdx.x % DGRP) * 8 + wid;
    if (grp >= 625) return;
    const int n0 = grp * 32;

    float* tile = tiles + wid * (32*65);
    {
        const float4* src = (const float4*)(g_agg + (size_t)plane*PL + (size_t)n0*64);
        #pragma unroll
        for (int j = 0; j < 16; j++) {
            int idx = j*32 + lane;
            float4 v = src[idx];
            float* tp = tile + (idx >> 4)*65 + (idx & 15)*4;
            tp[0] = v.x; tp[1] = v.y; tp[2] = v.z; tp[3] = v.w;
        }
    }
    __syncwarp();

    const float* arow = tile + lane*65;
    ull acc[32];
    #pragma unroll
    for (int k = 0; k < 32; k++) acc[k] = 0ull;
    #pragma unroll
    for (int c = 0; c < 64; c++) {
        ull a2 = pack2(arow[c]);
        const ulonglong2* wr = (const ulonglong2*)(swp + c*64);
        #pragma unroll
        for (int t = 0; t < 16; t++) {
            ulonglong2 wp = wr[t];
            ffma2(acc[2*t],   wp.x, a2);
            ffma2(acc[2*t+1], wp.y, a2);
        }
    }

    const float S = 0.0625f;
    const int n = n0 + lane;
    float* ob = out + (size_t)n*576;
    if (plane == 0) {
        float4* o4 = (float4*)ob;
        #pragma unroll
        for (int k = 0; k < 16; k++) {
            float2 lo = unpk(acc[2*k]), hi = unpk(acc[2*k+1]);
            o4[k] = make_float4(lo.x*S, lo.y*S, hi.x*S, hi.y*S);
        }
    } else if (plane < 4) {
        float* b = ob + 64 + (plane - 1);
        #pragma unroll
        for (int k = 0; k < 32; k++) {
            float2 f = unpk(acc[k]);
            b[3*(2*k)]   = f.x * S;
            b[3*(2*k+1)] = f.y * S;
        }
    } else {
        float* b = ob + 256 + (plane - 4);
        #pragma unroll
        for (int k = 0; k < 32; k++) {
            float2 f = unpk(acc[k]);
            b[5*(2*k)]   = f.x * S;
            b[5*(2*k+1)] = f.y * S;
        }
    }
}

// ---------------------------------------------------------------- launch
extern "C" void kernel_launch(void* const* d_in, const int* in_sizes, int n_in,
                              void* d_out, int out_size)
{
    const float* vectors    = (const float*)d_in[0];
    const float* node_feats = (const float*)d_in[1];
    const float* radial     = (const float*)d_in[2];
    const int*   senders    = (const int*)  d_in[3];
    const int*   receivers  = (const int*)  d_in[4];
    const float* w_up       = (const float*)d_in[5];
    const float* mlp_w1     = (const float*)d_in[6];
    const float* mlp_w2     = (const float*)d_in[7];
    const float* mlp_w3     = (const float*)d_in[8];
    const float* mlp_w4     = (const float*)d_in[9];
    const float* w_down0    = (const float*)d_in[10];
    const float* w_down1    = (const float*)d_in[11];
    const float* w_down2    = (const float*)d_in[12];
    float* out = (float*)d_out;

    const int D_SMEM = (4096 + 8*32*65) * 4;
    cudaFuncSetAttribute(down_kernel, cudaFuncAttributeMaxDynamicSharedMemorySize, D_SMEM);

    void* cntp = nullptr;
    cudaGetSymbolAddress(&cntp, g_cnt);
    cudaMemsetAsync(cntp, 0, NN * sizeof(int));

    hist_kernel<<<(NE + 255)/256, 256>>>(receivers);
    scan_kernel<<<1, 1024>>>();
    order_kernel<<<(NE + 255)/256, 256>>>(receivers);
    prep_kernel<<<168, 32>>>(mlp_w1, mlp_w2, mlp_w3, mlp_w4);
    up_kernel<<<NN/4, 256>>>(node_feats, w_up);
    edgeM_kernel<<<NE/(16*4), 128>>>(vectors, radial, senders);
    gather_kernel<<<(NN*32 + 127)/128, 128>>>();
    down_kernel<<<9*DGRP, 256, D_SMEM>>>(w_down0, w_down1, w_down2, out);
}

// round 7
// speedup vs baseline: 4.8350x; 1.0501x over previous
#include <cuda_runtime.h>
#include <cuda_bf16.h>
#include <cstdint>

#define NN 20000
#define NE 320000
#define CC 64
#define PL (NN*CC)

typedef unsigned long long ull;

// Scratch (allocation-free rule: __device__ globals)
__device__ __align__(16) float g_h[NN*CC];            // 5.1 MB
__device__ __align__(16) float g_agg[9*PL];           // 46 MB
__device__ __align__(16) float g_msg[(size_t)NE*192]; // 246 MB (receiver-sorted order)
__device__ __align__(16) float g_y[NE*8];             // 10 MB  (receiver-sorted order)
__device__ __align__(16) uint4 g_wfrag[168*32];       // 86 KB packed B fragments
__device__ int g_cnt[NN];
__device__ int g_off[NN+1];
__device__ int g_cur[NN];
__device__ int g_order[NE];

__device__ __forceinline__ float silu(float x) {
    return x * (1.0f / (1.0f + __expf(-x)));
}
__device__ __forceinline__ ull pack2(float x) {
    ull r; asm("mov.b64 %0, {%1, %1};" : "=l"(r) : "f"(x)); return r;
}
__device__ __forceinline__ void ffma2(ull& q, ull w, ull a) {
    asm("fma.rn.f32x2 %0, %1, %2, %0;" : "+l"(q) : "l"(w), "l"(a));
}
__device__ __forceinline__ float2 unpk(ull v) {
    float lo, hi; asm("mov.b64 {%0, %1}, %2;" : "=f"(lo), "=f"(hi) : "l"(v));
    return make_float2(lo, hi);
}

// pack (x0 -> low half, x1 -> high half) as bf16x2; return hi-word, write lo(residual)-word
__device__ __forceinline__ uint32_t split_pair(float x0, float x1, uint32_t& lw) {
    uint32_t hw;
    asm("cvt.rn.bf16x2.f32 %0, %1, %2;" : "=r"(hw) : "f"(x1), "f"(x0));
    float h0 = __uint_as_float(hw << 16);
    float h1 = __uint_as_float(hw & 0xffff0000u);
    asm("cvt.rn.bf16x2.f32 %0, %1, %2;" : "=r"(lw) : "f"(x1 - h1), "f"(x0 - h0));
    return hw;
}

__device__ __forceinline__ void mma16816(float c[4],
    uint32_t a0, uint32_t a1, uint32_t a2, uint32_t a3, uint32_t b0, uint32_t b1)
{
    asm volatile("mma.sync.aligned.m16n8k16.row.col.f32.bf16.bf16.f32 "
        "{%0,%1,%2,%3},{%4,%5,%6,%7},{%8,%9},{%0,%1,%2,%3};"
        : "+f"(c[0]), "+f"(c[1]), "+f"(c[2]), "+f"(c[3])
        : "r"(a0), "r"(a1), "r"(a2), "r"(a3), "r"(b0), "r"(b1));
}

// ---------------------------------------------------------------- prep: pack B fragments
// tile map: [0,8) L1 (kt=0) ; [8,40) L2 ; [40,72) L3 ; [72,168) L4 (kt*24+nt)
__global__ void prep_kernel(const float* __restrict__ w1, const float* __restrict__ w2,
                            const float* __restrict__ w3, const float* __restrict__ w4)
{
    const int tile = blockIdx.x;
    const int lane = threadIdx.x;
    const int g = lane >> 2, tig = lane & 3;
    const float* W; int K, Nc, kt, nt; float sc;
    if (tile < 8)        { W = w1; K = 8;  Nc = 64;  kt = 0;            nt = tile;          sc = 0.35355339059f; }
    else if (tile < 40)  { int t = tile-8;  W = w2; K = 64; Nc = 64;  kt = t >> 3;       nt = t & 7;          sc = 0.125f; }
    else if (tile < 72)  { int t = tile-40; W = w3; K = 64; Nc = 64;  kt = t >> 3;       nt = t & 7;          sc = 0.125f; }
    else                 { int t = tile-72; W = w4; K = 64; Nc = 192; kt = t / 24;       nt = t % 24;         sc = 0.001953125f; }
    const int n = nt*8 + g;
    const int k0 = kt*16 + 2*tig;
    float x00 = (k0   < K) ? W[(k0  )*Nc + n]*sc : 0.f;
    float x01 = (k0+1 < K) ? W[(k0+1)*Nc + n]*sc : 0.f;
    float x10 = (k0+8 < K) ? W[(k0+8)*Nc + n]*sc : 0.f;
    float x11 = (k0+9 < K) ? W[(k0+9)*Nc + n]*sc : 0.f;
    uint32_t l0, l1;
    uint32_t h0 = split_pair(x00, x01, l0);
    uint32_t h1 = split_pair(x10, x11, l1);
    g_wfrag[tile*32 + lane] = make_uint4(h0, h1, l0, l1);
}

// ---------------------------------------------------------------- h = nf @ w_up * (1/8)
__global__ void up_kernel(const float* __restrict__ nf, const float* __restrict__ wup) {
    __shared__ float ws[CC*CC];
    __shared__ float rows[4*CC];
    for (int i = threadIdx.x; i < CC*CC; i += blockDim.x) ws[i] = wup[i];
    int base = blockIdx.x * 4 * CC;
    rows[threadIdx.x] = nf[base + threadIdx.x];
    __syncthreads();
    int r = threadIdx.x >> 6;
    int c = threadIdx.x & 63;
    float acc = 0.f;
    #pragma unroll
    for (int i = 0; i < CC; i++) acc = fmaf(rows[r*CC + i], ws[i*CC + c], acc);
    g_h[base + threadIdx.x] = acc * 0.125f;
}

// ---------------------------------------------------------------- edgeM: full MLP on mma.sync bf16
__device__ __forceinline__ void layerK64(int tbase, int lane, float C[8][4],
                                         const uint32_t Ah[4][4], const uint32_t Al[4][4])
{
    #pragma unroll
    for (int nt = 0; nt < 8; nt++) {
        C[nt][0] = C[nt][1] = C[nt][2] = C[nt][3] = 0.f;
        #pragma unroll
        for (int kt = 0; kt < 4; kt++) {
            uint4 wf = g_wfrag[(tbase + kt*8 + nt)*32 + lane];
            mma16816(C[nt], Ah[kt][0], Ah[kt][1], Ah[kt][2], Ah[kt][3], wf.x, wf.y);
            mma16816(C[nt], Ah[kt][0], Ah[kt][1], Ah[kt][2], Ah[kt][3], wf.z, wf.w);
            mma16816(C[nt], Al[kt][0], Al[kt][1], Al[kt][2], Al[kt][3], wf.x, wf.y);
        }
    }
}

__device__ __forceinline__ void transition(const float C[8][4], uint32_t Ah[4][4], uint32_t Al[4][4])
{
    #pragma unroll
    for (int kt = 0; kt < 4; kt++) {
        const float* ca = C[2*kt];
        const float* cb = C[2*kt+1];
        Ah[kt][0] = split_pair(silu(ca[0]), silu(ca[1]), Al[kt][0]);
        Ah[kt][1] = split_pair(silu(ca[2]), silu(ca[3]), Al[kt][1]);
        Ah[kt][2] = split_pair(silu(cb[0]), silu(cb[1]), Al[kt][2]);
        Ah[kt][3] = split_pair(silu(cb[2]), silu(cb[3]), Al[kt][3]);
    }
}

// Processes edges in RECEIVER-SORTED order: position i -> edge g_order[i].
// msg / y are written at position i so the gather reads sequentially.
__global__ __launch_bounds__(128) void edgeM_kernel(
    const float* __restrict__ vectors, const float* __restrict__ radial,
    const int* __restrict__ senders)
{
    const int wt = blockIdx.x*4 + (threadIdx.x >> 5);   // 0..19999, 16 positions each
    const int lane = threadIdx.x & 31;
    const int g = lane >> 2, tig = lane & 3;
    const int base = wt*16;
    const int p0 = base + g, p1 = p0 + 8;               // sorted positions
    const int e0 = g_order[p0], e1 = g_order[p1];       // actual edges

    uint32_t Ah[4][4], Al[4][4];
    // L1 A fragments from radial (K=8, zero-padded to 16)
    {
        float2 r0 = *(const float2*)(radial + (size_t)e0*8 + 2*tig);
        float2 r1 = *(const float2*)(radial + (size_t)e1*8 + 2*tig);
        Ah[0][0] = split_pair(r0.x, r0.y, Al[0][0]);
        Ah[0][1] = split_pair(r1.x, r1.y, Al[0][1]);
        Ah[0][2] = 0; Ah[0][3] = 0; Al[0][2] = 0; Al[0][3] = 0;
    }

    float C[8][4];
    // ---- L1 (kt = 0 only, tiles 0..7) ----
    #pragma unroll
    for (int nt = 0; nt < 8; nt++) {
        C[nt][0] = C[nt][1] = C[nt][2] = C[nt][3] = 0.f;
        uint4 wf = g_wfrag[nt*32 + lane];
        mma16816(C[nt], Ah[0][0], Ah[0][1], Ah[0][2], Ah[0][3], wf.x, wf.y);
        mma16816(C[nt], Ah[0][0], Ah[0][1], Ah[0][2], Ah[0][3], wf.z, wf.w);
        mma16816(C[nt], Al[0][0], Al[0][1], Al[0][2], Al[0][3], wf.x, wf.y);
    }
    transition(C, Ah, Al);
    layerK64(8, lane, C, Ah, Al);    // L2
    transition(C, Ah, Al);
    layerK64(40, lane, C, Ah, Al);   // L3
    transition(C, Ah, Al);

    // ---- L4 (N=192 in 3 plane-chunks) + epilogue ----
    const int snd0 = senders[e0], snd1 = senders[e1];
    const float* h0r = g_h + (size_t)snd0*64;
    const float* h1r = g_h + (size_t)snd1*64;
    float* m0 = g_msg + (size_t)p0*192;   // sorted position
    float* m1 = g_msg + (size_t)p1*192;

    #pragma unroll
    for (int p = 0; p < 3; p++) {
        float D[8][4];
        #pragma unroll
        for (int ntl = 0; ntl < 8; ntl++) {
            D[ntl][0] = D[ntl][1] = D[ntl][2] = D[ntl][3] = 0.f;
            #pragma unroll
            for (int kt = 0; kt < 4; kt++) {
                uint4 wf = g_wfrag[(72 + kt*24 + p*8 + ntl)*32 + lane];
                mma16816(D[ntl], Ah[kt][0], Ah[kt][1], Ah[kt][2], Ah[kt][3], wf.x, wf.y);
                mma16816(D[ntl], Ah[kt][0], Ah[kt][1], Ah[kt][2], Ah[kt][3], wf.z, wf.w);
                mma16816(D[ntl], Al[kt][0], Al[kt][1], Al[kt][2], Al[kt][3], wf.x, wf.y);
            }
        }
        #pragma unroll
        for (int ntl = 0; ntl < 8; ntl++) {
            int col = 8*ntl + 2*tig;
            float2 h0 = *(const float2*)(h0r + col);
            float2 h1 = *(const float2*)(h1r + col);
            __stcs((float2*)(m0 + p*64 + col), make_float2(D[ntl][0]*h0.x, D[ntl][1]*h0.y));
            __stcs((float2*)(m1 + p*64 + col), make_float2(D[ntl][2]*h1.x, D[ntl][3]*h1.y));
        }
    }

    // spherical harmonics (lanes 0..15, one sorted position each)
    if (lane < 16) {
        const int e = g_order[base + lane];
        float vx = vectors[e*3], vy = vectors[e*3+1], vz = vectors[e*3+2];
        float inv = rsqrtf(vx*vx + vy*vy + vz*vz);
        float ux = vx*inv, uy = vy*inv, uz = vz*inv;
        const float SQ3 = 1.7320508075688772f, S15 = 3.872983346207417f;
        const float HS5 = 1.118033988749895f;
        float4* yp = (float4*)(g_y + (size_t)(base + lane)*8);
        __stcs(yp,   make_float4(SQ3*ux, SQ3*uy, SQ3*uz, S15*ux*uy));
        __stcs(yp+1, make_float4(S15*uy*uz, HS5*(3.f*uz*uz - 1.f), S15*ux*uz, 0.5f*S15*(ux*ux - uy*uy)));
    }
}

// ---------------------------------------------------------------- counting sort by receiver
__global__ void hist_kernel(const int* __restrict__ receivers) {
    int e = blockIdx.x * blockDim.x + threadIdx.x;
    if (e < NE) atomicAdd(&g_cnt[receivers[e]], 1);
}

__global__ void scan_kernel() {
    __shared__ int part[1024];
    const int t = threadIdx.x;
    const int base = t * 20;
    int sum = 0;
    if (t < 1000) {
        #pragma unroll
        for (int k = 0; k < 20; k++) sum += g_cnt[base + k];
    }
    part[t] = sum;
    __syncthreads();
    #pragma unroll
    for (int off = 1; off < 1024; off <<= 1) {
        int v = (t >= off) ? part[t - off] : 0;
        __syncthreads();
        part[t] += v;
        __syncthreads();
    }
    if (t < 1000) {
        int run = part[t] - sum;
        #pragma unroll
        for (int k = 0; k < 20; k++) {
            g_off[base + k] = run;
            g_cur[base + k] = run;
            run += g_cnt[base + k];
        }
    }
    if (t == 0) g_off[NN] = NE;
}

__global__ void order_kernel(const int* __restrict__ receivers) {
    int e = blockIdx.x * blockDim.x + threadIdx.x;
    if (e < NE) {
        int pos = atomicAdd(&g_cur[receivers[e]], 1);
        g_order[pos] = e;
    }
}

// ---------------------------------------------------------------- gather: warp per node, SEQUENTIAL msg reads
__global__ __launch_bounds__(128) void gather_kernel() {
    const int n = (blockIdx.x * 128 + threadIdx.x) >> 5;
    if (n >= NN) return;
    const int lane = threadIdx.x & 31;
    const int c0 = lane * 2;

    const int s = g_off[n], epos = g_off[n+1];

    float a0x=0.f, a0y=0.f;
    float a1x[3]={0,0,0}, a1y[3]={0,0,0};
    float a2x[5]={0,0,0,0,0}, a2y[5]={0,0,0,0,0};

    for (int i = s; i < epos; i++) {
        const float* mp = g_msg + (size_t)i*192;
        float2 t0 = __ldcs((const float2*)(mp + c0));
        float2 t1 = __ldcs((const float2*)(mp + 64 + c0));
        float2 t2 = __ldcs((const float2*)(mp + 128 + c0));
        const float4* yp = (const float4*)(g_y + (size_t)i*8);
        float4 ya = __ldcs(yp), yb = __ldcs(yp+1);
        float y1v[3] = {ya.x, ya.y, ya.z};
        float y2v[5] = {ya.w, yb.x, yb.y, yb.z, yb.w};
        a0x += t0.x; a0y += t0.y;
        #pragma unroll
        for (int m = 0; m < 3; m++) { a1x[m] = fmaf(t1.x, y1v[m], a1x[m]); a1y[m] = fmaf(t1.y, y1v[m], a1y[m]); }
        #pragma unroll
        for (int m = 0; m < 5; m++) { a2x[m] = fmaf(t2.x, y2v[m], a2x[m]); a2y[m] = fmaf(t2.y, y2v[m], a2y[m]); }
    }

    float* row = g_agg + (size_t)n*64 + c0;
    *(float2*)row = make_float2(a0x, a0y);
    #pragma unroll
    for (int m = 0; m < 3; m++)
        *(float2*)(row + (size_t)(1+m)*PL) = make_float2(a1x[m], a1y[m]);
    #pragma unroll
    for (int m = 0; m < 5; m++)
        *(float2*)(row + (size_t)(4+m)*PL) = make_float2(a2x[m], a2y[m]);
}

// ---------------------------------------------------------------- down projection
#define DGRP 79
__global__ __launch_bounds__(256) void down_kernel(const float* __restrict__ w0, const float* __restrict__ w1,
                                                   const float* __restrict__ w2, float* __restrict__ out)
{
    extern __shared__ float sm[];
    float* swp   = sm;            // 4096 floats
    float* tiles = sm + 4096;     // 8 * 32*65 floats

    const int plane = blockIdx.x / DGRP;
    const float* wsrc = (plane == 0) ? w0 : (plane < 4 ? w1 : w2);
    {
        float4* d = (float4*)swp; const float4* s = (const float4*)wsrc;
        for (int i = threadIdx.x; i < 1024; i += 256) d[i] = s[i];
    }
    __syncthreads();

    const int wid = threadIdx.x >> 5, lane = threadIdx.x & 31;
    const int grp = (blockIdx.x % DGRP) * 8 + wid;
    if (grp >= 625) return;
    const int n0 = grp * 32;

    float* tile = tiles + wid * (32*65);
    {
        const float4* src = (const float4*)(g_agg + (size_t)plane*PL + (size_t)n0*64);
        #pragma unroll
        for (int j = 0; j < 16; j++) {
            int idx = j*32 + lane;
            float4 v = src[idx];
            float* tp = tile + (idx >> 4)*65 + (idx & 15)*4;
            tp[0] = v.x; tp[1] = v.y; tp[2] = v.z; tp[3] = v.w;
        }
    }
    __syncwarp();

    const float* arow = tile + lane*65;
    ull acc[32];
    #pragma unroll
    for (int k = 0; k < 32; k++) acc[k] = 0ull;
    #pragma unroll
    for (int c = 0; c < 64; c++) {
        ull a2 = pack2(arow[c]);
        const ulonglong2* wr = (const ulonglong2*)(swp + c*64);
        #pragma unroll
        for (int t = 0; t < 16; t++) {
            ulonglong2 wp = wr[t];
            ffma2(acc[2*t],   wp.x, a2);
            ffma2(acc[2*t+1], wp.y, a2);
        }
    }

    const float S = 0.0625f;
    const int n = n0 + lane;
    float* ob = out + (size_t)n*576;
    if (plane == 0) {
        float4* o4 = (float4*)ob;
        #pragma unroll
        for (int k = 0; k < 16; k++) {
            float2 lo = unpk(acc[2*k]), hi = unpk(acc[2*k+1]);
            o4[k] = make_float4(lo.x*S, lo.y*S, hi.x*S, hi.y*S);
        }
    } else if (plane < 4) {
        float* b = ob + 64 + (plane - 1);
        #pragma unroll
        for (int k = 0; k < 32; k++) {
            float2 f = unpk(acc[k]);
            b[3*(2*k)]   = f.x * S;
            b[3*(2*k+1)] = f.y * S;
        }
    } else {
        float* b = ob + 256 + (plane - 4);
        #pragma unroll
        for (int k = 0; k < 32; k++) {
            float2 f = unpk(acc[k]);
            b[5*(2*k)]   = f.x * S;
            b[5*(2*k+1)] = f.y * S;
        }
    }
}

// ---------------------------------------------------------------- launch
extern "C" void kernel_launch(void* const* d_in, const int* in_sizes, int n_in,
                              void* d_out, int out_size)
{
    const float* vectors    = (const float*)d_in[0];
    const float* node_feats = (const float*)d_in[1];
    const float* radial     = (const float*)d_in[2];
    const int*   senders    = (const int*)  d_in[3];
    const int*   receivers  = (const int*)  d_in[4];
    const float* w_up       = (const float*)d_in[5];
    const float* mlp_w1     = (const float*)d_in[6];
    const float* mlp_w2     = (const float*)d_in[7];
    const float* mlp_w3     = (const float*)d_in[8];
    const float* mlp_w4     = (const float*)d_in[9];
    const float* w_down0    = (const float*)d_in[10];
    const float* w_down1    = (const float*)d_in[11];
    const float* w_down2    = (const float*)d_in[12];
    float* out = (float*)d_out;

    const int D_SMEM = (4096 + 8*32*65) * 4;
    cudaFuncSetAttribute(down_kernel, cudaFuncAttributeMaxDynamicSharedMemorySize, D_SMEM);

    void* cntp = nullptr;
    cudaGetSymbolAddress(&cntp, g_cnt);
    cudaMemsetAsync(cntp, 0, NN * sizeof(int));

    hist_kernel<<<(NE + 255)/256, 256>>>(receivers);
    scan_kernel<<<1, 1024>>>();
    order_kernel<<<(NE + 255)/256, 256>>>(receivers);
    prep_kernel<<<168, 32>>>(mlp_w1, mlp_w2, mlp_w3, mlp_w4);
    up_kernel<<<NN/4, 256>>>(node_feats, w_up);
    edgeM_kernel<<<NE/(16*4), 128>>>(vectors, radial, senders);
    gather_kernel<<<(NN*32 + 127)/128, 128>>>();
    down_kernel<<<9*DGRP, 256, D_SMEM>>>(w_down0, w_down1, w_down2, out);
}

// round 8
// speedup vs baseline: 5.5521x; 1.1483x over previous
#include <cuda_runtime.h>
#include <cuda_bf16.h>
#include <cstdint>

#define NN 20000
#define NE 320000
#define CC 64
#define PL (NN*CC)

typedef unsigned long long ull;

// Scratch (allocation-free rule: __device__ globals)
__device__ __align__(16) float g_h[NN*CC];            // 5.1 MB
__device__ __align__(16) float g_agg[9*PL];           // 46 MB
__device__ __align__(16) float g_msg[(size_t)NE*192]; // 246 MB (receiver-sorted order)
__device__ __align__(16) float g_y[NE*8];             // 10 MB  (receiver-sorted order)
__device__ __align__(16) uint4 g_wfrag[168*32];       // 86 KB packed B fragments
__device__ int g_cnt[NN];
__device__ int g_off[NN+1];
__device__ int g_cur[NN];
__device__ int g_order[NE];

// silu via hardware tanh: x*sigmoid(x) = 0.5x*tanh(0.5x) + 0.5x   (3 instr, 1 MUFU)
__device__ __forceinline__ float silu(float x) {
    float hx = 0.5f * x;
    float t;
    asm("tanh.approx.f32 %0, %1;" : "=f"(t) : "f"(hx));
    return fmaf(hx, t, hx);
}
__device__ __forceinline__ ull pack2(float x) {
    ull r; asm("mov.b64 %0, {%1, %1};" : "=l"(r) : "f"(x)); return r;
}
__device__ __forceinline__ void ffma2(ull& q, ull w, ull a) {
    asm("fma.rn.f32x2 %0, %1, %2, %0;" : "+l"(q) : "l"(w), "l"(a));
}
__device__ __forceinline__ float2 unpk(ull v) {
    float lo, hi; asm("mov.b64 {%0, %1}, %2;" : "=f"(lo), "=f"(hi) : "l"(v));
    return make_float2(lo, hi);
}

// pack (x0 -> low half, x1 -> high half) as bf16x2; return hi-word, write lo(residual)-word
__device__ __forceinline__ uint32_t split_pair(float x0, float x1, uint32_t& lw) {
    uint32_t hw;
    asm("cvt.rn.bf16x2.f32 %0, %1, %2;" : "=r"(hw) : "f"(x1), "f"(x0));
    float h0 = __uint_as_float(hw << 16);
    float h1 = __uint_as_float(hw & 0xffff0000u);
    asm("cvt.rn.bf16x2.f32 %0, %1, %2;" : "=r"(lw) : "f"(x1 - h1), "f"(x0 - h0));
    return hw;
}

__device__ __forceinline__ void mma16816(float c[4],
    uint32_t a0, uint32_t a1, uint32_t a2, uint32_t a3, uint32_t b0, uint32_t b1)
{
    asm volatile("mma.sync.aligned.m16n8k16.row.col.f32.bf16.bf16.f32 "
        "{%0,%1,%2,%3},{%4,%5,%6,%7},{%8,%9},{%0,%1,%2,%3};"
        : "+f"(c[0]), "+f"(c[1]), "+f"(c[2]), "+f"(c[3])
        : "r"(a0), "r"(a1), "r"(a2), "r"(a3), "r"(b0), "r"(b1));
}

// ---------------------------------------------------------------- prep: pack B fragments
// tile map: [0,8) L1 (kt=0) ; [8,40) L2 ; [40,72) L3 ; [72,168) L4 (kt*24+nt)
__global__ void prep_kernel(const float* __restrict__ w1, const float* __restrict__ w2,
                            const float* __restrict__ w3, const float* __restrict__ w4)
{
    const int tile = blockIdx.x;
    const int lane = threadIdx.x;
    const int g = lane >> 2, tig = lane & 3;
    const float* W; int K, Nc, kt, nt; float sc;
    if (tile < 8)        { W = w1; K = 8;  Nc = 64;  kt = 0;            nt = tile;          sc = 0.35355339059f; }
    else if (tile < 40)  { int t = tile-8;  W = w2; K = 64; Nc = 64;  kt = t >> 3;       nt = t & 7;          sc = 0.125f; }
    else if (tile < 72)  { int t = tile-40; W = w3; K = 64; Nc = 64;  kt = t >> 3;       nt = t & 7;          sc = 0.125f; }
    else                 { int t = tile-72; W = w4; K = 64; Nc = 192; kt = t / 24;       nt = t % 24;         sc = 0.001953125f; }
    const int n = nt*8 + g;
    const int k0 = kt*16 + 2*tig;
    float x00 = (k0   < K) ? W[(k0  )*Nc + n]*sc : 0.f;
    float x01 = (k0+1 < K) ? W[(k0+1)*Nc + n]*sc : 0.f;
    float x10 = (k0+8 < K) ? W[(k0+8)*Nc + n]*sc : 0.f;
    float x11 = (k0+9 < K) ? W[(k0+9)*Nc + n]*sc : 0.f;
    uint32_t l0, l1;
    uint32_t h0 = split_pair(x00, x01, l0);
    uint32_t h1 = split_pair(x10, x11, l1);
    g_wfrag[tile*32 + lane] = make_uint4(h0, h1, l0, l1);
}

// ---------------------------------------------------------------- h = nf @ w_up * (1/8)
__global__ void up_kernel(const float* __restrict__ nf, const float* __restrict__ wup) {
    __shared__ float ws[CC*CC];
    __shared__ float rows[4*CC];
    for (int i = threadIdx.x; i < CC*CC; i += blockDim.x) ws[i] = wup[i];
    int base = blockIdx.x * 4 * CC;
    rows[threadIdx.x] = nf[base + threadIdx.x];
    __syncthreads();
    int r = threadIdx.x >> 6;
    int c = threadIdx.x & 63;
    float acc = 0.f;
    #pragma unroll
    for (int i = 0; i < CC; i++) acc = fmaf(rows[r*CC + i], ws[i*CC + c], acc);
    g_h[base + threadIdx.x] = acc * 0.125f;
}

// ---------------------------------------------------------------- edgeM: full MLP on mma.sync bf16
__device__ __forceinline__ void layerK64(int tbase, int lane, float C[8][4],
                                         const uint32_t Ah[4][4], const uint32_t Al[4][4])
{
    #pragma unroll
    for (int nt = 0; nt < 8; nt++) {
        C[nt][0] = C[nt][1] = C[nt][2] = C[nt][3] = 0.f;
        #pragma unroll
        for (int kt = 0; kt < 4; kt++) {
            uint4 wf = g_wfrag[(tbase + kt*8 + nt)*32 + lane];
            mma16816(C[nt], Ah[kt][0], Ah[kt][1], Ah[kt][2], Ah[kt][3], wf.x, wf.y);
            mma16816(C[nt], Ah[kt][0], Ah[kt][1], Ah[kt][2], Ah[kt][3], wf.z, wf.w);
            mma16816(C[nt], Al[kt][0], Al[kt][1], Al[kt][2], Al[kt][3], wf.x, wf.y);
        }
    }
}

__device__ __forceinline__ void transition(const float C[8][4], uint32_t Ah[4][4], uint32_t Al[4][4])
{
    #pragma unroll
    for (int kt = 0; kt < 4; kt++) {
        const float* ca = C[2*kt];
        const float* cb = C[2*kt+1];
        Ah[kt][0] = split_pair(silu(ca[0]), silu(ca[1]), Al[kt][0]);
        Ah[kt][1] = split_pair(silu(ca[2]), silu(ca[3]), Al[kt][1]);
        Ah[kt][2] = split_pair(silu(cb[0]), silu(cb[1]), Al[kt][2]);
        Ah[kt][3] = split_pair(silu(cb[2]), silu(cb[3]), Al[kt][3]);
    }
}

// Processes edges in RECEIVER-SORTED order: position i -> edge g_order[i].
// msg / y are written at position i so the gather reads sequentially.
__global__ __launch_bounds__(128) void edgeM_kernel(
    const float* __restrict__ vectors, const float* __restrict__ radial,
    const int* __restrict__ senders)
{
    const int wt = blockIdx.x*4 + (threadIdx.x >> 5);   // 0..19999, 16 positions each
    const int lane = threadIdx.x & 31;
    const int g = lane >> 2, tig = lane & 3;
    const int base = wt*16;
    const int p0 = base + g, p1 = p0 + 8;               // sorted positions
    const int e0 = g_order[p0], e1 = g_order[p1];       // actual edges

    uint32_t Ah[4][4], Al[4][4];
    // L1 A fragments from radial (K=8, zero-padded to 16)
    {
        float2 r0 = *(const float2*)(radial + (size_t)e0*8 + 2*tig);
        float2 r1 = *(const float2*)(radial + (size_t)e1*8 + 2*tig);
        Ah[0][0] = split_pair(r0.x, r0.y, Al[0][0]);
        Ah[0][1] = split_pair(r1.x, r1.y, Al[0][1]);
        Ah[0][2] = 0; Ah[0][3] = 0; Al[0][2] = 0; Al[0][3] = 0;
    }

    float C[8][4];
    // ---- L1 (kt = 0 only, tiles 0..7) ----
    #pragma unroll
    for (int nt = 0; nt < 8; nt++) {
        C[nt][0] = C[nt][1] = C[nt][2] = C[nt][3] = 0.f;
        uint4 wf = g_wfrag[nt*32 + lane];
        mma16816(C[nt], Ah[0][0], Ah[0][1], Ah[0][2], Ah[0][3], wf.x, wf.y);
        mma16816(C[nt], Ah[0][0], Ah[0][1], Ah[0][2], Ah[0][3], wf.z, wf.w);
        mma16816(C[nt], Al[0][0], Al[0][1], Al[0][2], Al[0][3], wf.x, wf.y);
    }
    transition(C, Ah, Al);
    layerK64(8, lane, C, Ah, Al);    // L2
    transition(C, Ah, Al);
    layerK64(40, lane, C, Ah, Al);   // L3
    transition(C, Ah, Al);

    // ---- L4 (N=192 in 3 plane-chunks) + epilogue ----
    const int snd0 = senders[e0], snd1 = senders[e1];
    const float* h0r = g_h + (size_t)snd0*64;
    const float* h1r = g_h + (size_t)snd1*64;
    float* m0 = g_msg + (size_t)p0*192;   // sorted position
    float* m1 = g_msg + (size_t)p1*192;

    #pragma unroll
    for (int p = 0; p < 3; p++) {
        float D[8][4];
        #pragma unroll
        for (int ntl = 0; ntl < 8; ntl++) {
            D[ntl][0] = D[ntl][1] = D[ntl][2] = D[ntl][3] = 0.f;
            #pragma unroll
            for (int kt = 0; kt < 4; kt++) {
                uint4 wf = g_wfrag[(72 + kt*24 + p*8 + ntl)*32 + lane];
                mma16816(D[ntl], Ah[kt][0], Ah[kt][1], Ah[kt][2], Ah[kt][3], wf.x, wf.y);
                mma16816(D[ntl], Ah[kt][0], Ah[kt][1], Ah[kt][2], Ah[kt][3], wf.z, wf.w);
                mma16816(D[ntl], Al[kt][0], Al[kt][1], Al[kt][2], Al[kt][3], wf.x, wf.y);
            }
        }
        #pragma unroll
        for (int ntl = 0; ntl < 8; ntl++) {
            int col = 8*ntl + 2*tig;
            float2 h0 = *(const float2*)(h0r + col);
            float2 h1 = *(const float2*)(h1r + col);
            __stcs((float2*)(m0 + p*64 + col), make_float2(D[ntl][0]*h0.x, D[ntl][1]*h0.y));
            __stcs((float2*)(m1 + p*64 + col), make_float2(D[ntl][2]*h1.x, D[ntl][3]*h1.y));
        }
    }

    // spherical harmonics (lanes 0..15, one sorted position each)
    if (lane < 16) {
        const int e = g_order[base + lane];
        float vx = vectors[e*3], vy = vectors[e*3+1], vz = vectors[e*3+2];
        float inv = rsqrtf(vx*vx + vy*vy + vz*vz);
        float ux = vx*inv, uy = vy*inv, uz = vz*inv;
        const float SQ3 = 1.7320508075688772f, S15 = 3.872983346207417f;
        const float HS5 = 1.118033988749895f;
        float4* yp = (float4*)(g_y + (size_t)(base + lane)*8);
        __stcs(yp,   make_float4(SQ3*ux, SQ3*uy, SQ3*uz, S15*ux*uy));
        __stcs(yp+1, make_float4(S15*uy*uz, HS5*(3.f*uz*uz - 1.f), S15*ux*uz, 0.5f*S15*(ux*ux - uy*uy)));
    }
}

// ---------------------------------------------------------------- counting sort by receiver
__global__ void hist_kernel(const int* __restrict__ receivers) {
    int e = blockIdx.x * blockDim.x + threadIdx.x;
    if (e < NE) atomicAdd(&g_cnt[receivers[e]], 1);
}

__global__ void scan_kernel() {
    __shared__ int part[1024];
    const int t = threadIdx.x;
    const int base = t * 20;
    int sum = 0;
    if (t < 1000) {
        #pragma unroll
        for (int k = 0; k < 20; k++) sum += g_cnt[base + k];
    }
    part[t] = sum;
    __syncthreads();
    #pragma unroll
    for (int off = 1; off < 1024; off <<= 1) {
        int v = (t >= off) ? part[t - off] : 0;
        __syncthreads();
        part[t] += v;
        __syncthreads();
    }
    if (t < 1000) {
        int run = part[t] - sum;
        #pragma unroll
        for (int k = 0; k < 20; k++) {
            g_off[base + k] = run;
            g_cur[base + k] = run;
            run += g_cnt[base + k];
        }
    }
    if (t == 0) g_off[NN] = NE;
}

__global__ void order_kernel(const int* __restrict__ receivers) {
    int e = blockIdx.x * blockDim.x + threadIdx.x;
    if (e < NE) {
        int pos = atomicAdd(&g_cur[receivers[e]], 1);
        g_order[pos] = e;
    }
}

// ---------------------------------------------------------------- gather: warp per node, SEQUENTIAL msg reads
__global__ __launch_bounds__(128) void gather_kernel() {
    const int n = (blockIdx.x * 128 + threadIdx.x) >> 5;
    if (n >= NN) return;
    const int lane = threadIdx.x & 31;
    const int c0 = lane * 2;

    const int s = g_off[n], epos = g_off[n+1];

    float a0x=0.f, a0y=0.f;
    float a1x[3]={0,0,0}, a1y[3]={0,0,0};
    float a2x[5]={0,0,0,0,0}, a2y[5]={0,0,0,0,0};

    for (int i = s; i < epos; i++) {
        const float* mp = g_msg + (size_t)i*192;
        float2 t0 = __ldcs((const float2*)(mp + c0));
        float2 t1 = __ldcs((const float2*)(mp + 64 + c0));
        float2 t2 = __ldcs((const float2*)(mp + 128 + c0));
        const float4* yp = (const float4*)(g_y + (size_t)i*8);
        float4 ya = __ldcs(yp), yb = __ldcs(yp+1);
        float y1v[3] = {ya.x, ya.y, ya.z};
        float y2v[5] = {ya.w, yb.x, yb.y, yb.z, yb.w};
        a0x += t0.x; a0y += t0.y;
        #pragma unroll
        for (int m = 0; m < 3; m++) { a1x[m] = fmaf(t1.x, y1v[m], a1x[m]); a1y[m] = fmaf(t1.y, y1v[m], a1y[m]); }
        #pragma unroll
        for (int m = 0; m < 5; m++) { a2x[m] = fmaf(t2.x, y2v[m], a2x[m]); a2y[m] = fmaf(t2.y, y2v[m], a2y[m]); }
    }

    float* row = g_agg + (size_t)n*64 + c0;
    *(float2*)row = make_float2(a0x, a0y);
    #pragma unroll
    for (int m = 0; m < 3; m++)
        *(float2*)(row + (size_t)(1+m)*PL) = make_float2(a1x[m], a1y[m]);
    #pragma unroll
    for (int m = 0; m < 5; m++)
        *(float2*)(row + (size_t)(4+m)*PL) = make_float2(a2x[m], a2y[m]);
}

// ---------------------------------------------------------------- down projection
#define DGRP 79
__global__ __launch_bounds__(256) void down_kernel(const float* __restrict__ w0, const float* __restrict__ w1,
                                                   const float* __restrict__ w2, float* __restrict__ out)
{
    extern __shared__ float sm[];
    float* swp   = sm;            // 4096 floats
    float* tiles = sm + 4096;     // 8 * 32*65 floats

    const int plane = blockIdx.x / DGRP;
    const float* wsrc = (plane == 0) ? w0 : (plane < 4 ? w1 : w2);
    {
        float4* d = (float4*)swp; const float4* s = (const float4*)wsrc;
        for (int i = threadIdx.x; i < 1024; i += 256) d[i] = s[i];
    }
    __syncthreads();

    const int wid = threadIdx.x >> 5, lane = threadIdx.x & 31;
    const int grp = (blockIdx.x % DGRP) * 8 + wid;
    if (grp >= 625) return;
    const int n0 = grp * 32;

    float* tile = tiles + wid * (32*65);
    {
        const float4* src = (const float4*)(g_agg + (size_t)plane*PL + (size_t)n0*64);
        #pragma unroll
        for (int j = 0; j < 16; j++) {
            int idx = j*32 + lane;
            float4 v = src[idx];
            float* tp = tile + (idx >> 4)*65 + (idx & 15)*4;
            tp[0] = v.x; tp[1] = v.y; tp[2] = v.z; tp[3] = v.w;
        }
    }
    __syncwarp();

    const float* arow = tile + lane*65;
    ull acc[32];
    #pragma unroll
    for (int k = 0; k < 32; k++) acc[k] = 0ull;
    #pragma unroll
    for (int c = 0; c < 64; c++) {
        ull a2 = pack2(arow[c]);
        const ulonglong2* wr = (const ulonglong2*)(swp + c*64);
        #pragma unroll
        for (int t = 0; t < 16; t++) {
            ulonglong2 wp = wr[t];
            ffma2(acc[2*t],   wp.x, a2);
            ffma2(acc[2*t+1], wp.y, a2);
        }
    }

    const float S = 0.0625f;
    const int n = n0 + lane;
    float* ob = out + (size_t)n*576;
    if (plane == 0) {
        float4* o4 = (float4*)ob;
        #pragma unroll
        for (int k = 0; k < 16; k++) {
            float2 lo = unpk(acc[2*k]), hi = unpk(acc[2*k+1]);
            o4[k] = make_float4(lo.x*S, lo.y*S, hi.x*S, hi.y*S);
        }
    } else if (plane < 4) {
        float* b = ob + 64 + (plane - 1);
        #pragma unroll
        for (int k = 0; k < 32; k++) {
            float2 f = unpk(acc[k]);
            b[3*(2*k)]   = f.x * S;
            b[3*(2*k+1)] = f.y * S;
        }
    } else {
        float* b = ob + 256 + (plane - 4);
        #pragma unroll
        for (int k = 0; k < 32; k++) {
            float2 f = unpk(acc[k]);
            b[5*(2*k)]   = f.x * S;
            b[5*(2*k+1)] = f.y * S;
        }
    }
}

// ---------------------------------------------------------------- launch
extern "C" void kernel_launch(void* const* d_in, const int* in_sizes, int n_in,
                              void* d_out, int out_size)
{
    const float* vectors    = (const float*)d_in[0];
    const float* node_feats = (const float*)d_in[1];
    const float* radial     = (const float*)d_in[2];
    const int*   senders    = (const int*)  d_in[3];
    const int*   receivers  = (const int*)  d_in[4];
    const float* w_up       = (const float*)d_in[5];
    const float* mlp_w1     = (const float*)d_in[6];
    const float* mlp_w2     = (const float*)d_in[7];
    const float* mlp_w3     = (const float*)d_in[8];
    const float* mlp_w4     = (const float*)d_in[9];
    const float* w_down0    = (const float*)d_in[10];
    const float* w_down1    = (const float*)d_in[11];
    const float* w_down2    = (const float*)d_in[12];
    float* out = (float*)d_out;

    const int D_SMEM = (4096 + 8*32*65) * 4;
    cudaFuncSetAttribute(down_kernel, cudaFuncAttributeMaxDynamicSharedMemorySize, D_SMEM);

    void* cntp = nullptr;
    cudaGetSymbolAddress(&cntp, g_cnt);
    cudaMemsetAsync(cntp, 0, NN * sizeof(int));

    hist_kernel<<<(NE + 255)/256, 256>>>(receivers);
    scan_kernel<<<1, 1024>>>();
    order_kernel<<<(NE + 255)/256, 256>>>(receivers);
    prep_kernel<<<168, 32>>>(mlp_w1, mlp_w2, mlp_w3, mlp_w4);
    up_kernel<<<NN/4, 256>>>(node_feats, w_up);
    edgeM_kernel<<<NE/(16*4), 128>>>(vectors, radial, senders);
    gather_kernel<<<(NN*32 + 127)/128, 128>>>();
    down_kernel<<<9*DGRP, 256, D_SMEM>>>(w_down0, w_down1, w_down2, out);
}

// round 9
// speedup vs baseline: 6.6325x; 1.1946x over previous
#include <cuda_runtime.h>
#include <cuda_bf16.h>
#include <cstdint>

#define NN 20000
#define NE 320000
#define CC 64
#define PL (NN*CC)

typedef unsigned long long ull;

// Scratch (allocation-free rule: __device__ globals)
__device__ __align__(16) float g_h[NN*CC];        // 5.1 MB
__device__ __align__(16) float g_agg[9*PL];       // 46 MB (atomic target, planar)
__device__ __align__(16) uint4 g_wfrag[168*32];   // 86 KB packed B fragments
__device__ int g_cnt[NN];
__device__ int g_off[NN+1];
__device__ int g_cur[NN];
__device__ int g_order[NE];

// silu via hardware tanh: x*sigmoid(x) = 0.5x*tanh(0.5x) + 0.5x
__device__ __forceinline__ float silu(float x) {
    float hx = 0.5f * x;
    float t;
    asm("tanh.approx.f32 %0, %1;" : "=f"(t) : "f"(hx));
    return fmaf(hx, t, hx);
}
__device__ __forceinline__ ull pack2(float x) {
    ull r; asm("mov.b64 %0, {%1, %1};" : "=l"(r) : "f"(x)); return r;
}
__device__ __forceinline__ void ffma2(ull& q, ull w, ull a) {
    asm("fma.rn.f32x2 %0, %1, %2, %0;" : "+l"(q) : "l"(w), "l"(a));
}
__device__ __forceinline__ float2 unpk(ull v) {
    float lo, hi; asm("mov.b64 {%0, %1}, %2;" : "=f"(lo), "=f"(hi) : "l"(v));
    return make_float2(lo, hi);
}
__device__ __forceinline__ void red2(float* p, float a, float b) {
    asm volatile("red.global.add.v2.f32 [%0], {%1,%2};" :: "l"(p), "f"(a), "f"(b) : "memory");
}

// pack (x0 -> low half, x1 -> high half) as bf16x2; return hi-word, write lo(residual)-word
__device__ __forceinline__ uint32_t split_pair(float x0, float x1, uint32_t& lw) {
    uint32_t hw;
    asm("cvt.rn.bf16x2.f32 %0, %1, %2;" : "=r"(hw) : "f"(x1), "f"(x0));
    float h0 = __uint_as_float(hw << 16);
    float h1 = __uint_as_float(hw & 0xffff0000u);
    asm("cvt.rn.bf16x2.f32 %0, %1, %2;" : "=r"(lw) : "f"(x1 - h1), "f"(x0 - h0));
    return hw;
}

__device__ __forceinline__ void mma16816(float c[4],
    uint32_t a0, uint32_t a1, uint32_t a2, uint32_t a3, uint32_t b0, uint32_t b1)
{
    asm volatile("mma.sync.aligned.m16n8k16.row.col.f32.bf16.bf16.f32 "
        "{%0,%1,%2,%3},{%4,%5,%6,%7},{%8,%9},{%0,%1,%2,%3};"
        : "+f"(c[0]), "+f"(c[1]), "+f"(c[2]), "+f"(c[3])
        : "r"(a0), "r"(a1), "r"(a2), "r"(a3), "r"(b0), "r"(b1));
}

// ---------------------------------------------------------------- prep: pack B fragments
__global__ void prep_kernel(const float* __restrict__ w1, const float* __restrict__ w2,
                            const float* __restrict__ w3, const float* __restrict__ w4)
{
    const int tile = blockIdx.x;
    const int lane = threadIdx.x;
    const int g = lane >> 2, tig = lane & 3;
    const float* W; int K, Nc, kt, nt; float sc;
    if (tile < 8)        { W = w1; K = 8;  Nc = 64;  kt = 0;            nt = tile;          sc = 0.35355339059f; }
    else if (tile < 40)  { int t = tile-8;  W = w2; K = 64; Nc = 64;  kt = t >> 3;       nt = t & 7;          sc = 0.125f; }
    else if (tile < 72)  { int t = tile-40; W = w3; K = 64; Nc = 64;  kt = t >> 3;       nt = t & 7;          sc = 0.125f; }
    else                 { int t = tile-72; W = w4; K = 64; Nc = 192; kt = t / 24;       nt = t % 24;         sc = 0.001953125f; }
    const int n = nt*8 + g;
    const int k0 = kt*16 + 2*tig;
    float x00 = (k0   < K) ? W[(k0  )*Nc + n]*sc : 0.f;
    float x01 = (k0+1 < K) ? W[(k0+1)*Nc + n]*sc : 0.f;
    float x10 = (k0+8 < K) ? W[(k0+8)*Nc + n]*sc : 0.f;
    float x11 = (k0+9 < K) ? W[(k0+9)*Nc + n]*sc : 0.f;
    uint32_t l0, l1;
    uint32_t h0 = split_pair(x00, x01, l0);
    uint32_t h1 = split_pair(x10, x11, l1);
    g_wfrag[tile*32 + lane] = make_uint4(h0, h1, l0, l1);
}

// ---------------------------------------------------------------- h = nf @ w_up * (1/8)
__global__ void up_kernel(const float* __restrict__ nf, const float* __restrict__ wup) {
    __shared__ float ws[CC*CC];
    __shared__ float rows[4*CC];
    for (int i = threadIdx.x; i < CC*CC; i += blockDim.x) ws[i] = wup[i];
    int base = blockIdx.x * 4 * CC;
    rows[threadIdx.x] = nf[base + threadIdx.x];
    __syncthreads();
    int r = threadIdx.x >> 6;
    int c = threadIdx.x & 63;
    float acc = 0.f;
    #pragma unroll
    for (int i = 0; i < CC; i++) acc = fmaf(rows[r*CC + i], ws[i*CC + c], acc);
    g_h[base + threadIdx.x] = acc * 0.125f;
}

// ---------------------------------------------------------------- edgeM helpers
__device__ __forceinline__ void layerK64(int tbase, int lane, float C[8][4],
                                         const uint32_t Ah[4][4], const uint32_t Al[4][4])
{
    #pragma unroll
    for (int nt = 0; nt < 8; nt++) {
        C[nt][0] = C[nt][1] = C[nt][2] = C[nt][3] = 0.f;
        #pragma unroll
        for (int kt = 0; kt < 4; kt++) {
            uint4 wf = g_wfrag[(tbase + kt*8 + nt)*32 + lane];
            mma16816(C[nt], Ah[kt][0], Ah[kt][1], Ah[kt][2], Ah[kt][3], wf.x, wf.y);
            mma16816(C[nt], Ah[kt][0], Ah[kt][1], Ah[kt][2], Ah[kt][3], wf.z, wf.w);
            mma16816(C[nt], Al[kt][0], Al[kt][1], Al[kt][2], Al[kt][3], wf.x, wf.y);
        }
    }
}

__device__ __forceinline__ void transition(const float C[8][4], uint32_t Ah[4][4], uint32_t Al[4][4])
{
    #pragma unroll
    for (int kt = 0; kt < 4; kt++) {
        const float* ca = C[2*kt];
        const float* cb = C[2*kt+1];
        Ah[kt][0] = split_pair(silu(ca[0]), silu(ca[1]), Al[kt][0]);
        Ah[kt][1] = split_pair(silu(ca[2]), silu(ca[3]), Al[kt][1]);
        Ah[kt][2] = split_pair(silu(cb[0]), silu(cb[1]), Al[kt][2]);
        Ah[kt][3] = split_pair(silu(cb[2]), silu(cb[3]), Al[kt][3]);
    }
}

// tile row stride (floats); even for 8B-aligned float2, 194%32=2 limits bank conflicts
#define TROW 194
#define TILE_F (16*TROW)          // per-warp t tile
#define EY_OFF (4*TILE_F)         // y: 4 warps * 128
#define ESMEM_F (4*TILE_F + 4*128 + 4*16)

// ---------------------------------------------------------------- edgeM: MLP (mma) + fused segmented scatter
// Processes edges in receiver-sorted order; per-warp 16 edges span few receivers.
__global__ __launch_bounds__(128) void edgeM_kernel(
    const float* __restrict__ vectors, const float* __restrict__ radial,
    const int* __restrict__ senders, const int* __restrict__ receivers)
{
    extern __shared__ float esm[];
    const int wid = threadIdx.x >> 5;
    const int lane = threadIdx.x & 31;
    float* tw = esm + wid*TILE_F;
    float* yw = esm + EY_OFF + wid*128;
    int*   rcw = (int*)(esm + EY_OFF + 4*128) + wid*16;

    const int wt = blockIdx.x*4 + wid;                  // 0..19999
    const int g = lane >> 2, tig = lane & 3;
    const int base = wt*16;
    const int p0 = base + g, p1 = p0 + 8;               // sorted positions
    const int e0 = g_order[p0], e1 = g_order[p1];       // actual edges

    uint32_t Ah[4][4], Al[4][4];
    {
        float2 r0 = *(const float2*)(radial + (size_t)e0*8 + 2*tig);
        float2 r1 = *(const float2*)(radial + (size_t)e1*8 + 2*tig);
        Ah[0][0] = split_pair(r0.x, r0.y, Al[0][0]);
        Ah[0][1] = split_pair(r1.x, r1.y, Al[0][1]);
        Ah[0][2] = 0; Ah[0][3] = 0; Al[0][2] = 0; Al[0][3] = 0;
    }

    float C[8][4];
    // ---- L1 ----
    #pragma unroll
    for (int nt = 0; nt < 8; nt++) {
        C[nt][0] = C[nt][1] = C[nt][2] = C[nt][3] = 0.f;
        uint4 wf = g_wfrag[nt*32 + lane];
        mma16816(C[nt], Ah[0][0], Ah[0][1], Ah[0][2], Ah[0][3], wf.x, wf.y);
        mma16816(C[nt], Ah[0][0], Ah[0][1], Ah[0][2], Ah[0][3], wf.z, wf.w);
        mma16816(C[nt], Al[0][0], Al[0][1], Al[0][2], Al[0][3], wf.x, wf.y);
    }
    transition(C, Ah, Al);
    layerK64(8, lane, C, Ah, Al);    // L2
    transition(C, Ah, Al);
    layerK64(40, lane, C, Ah, Al);   // L3
    transition(C, Ah, Al);

    // ---- L4 (N=192) -> smem tile (t = D * h * KSC already folded: KSC in wfrag scale) ----
    const int snd0 = senders[e0], snd1 = senders[e1];
    const float* h0r = g_h + (size_t)snd0*64;
    const float* h1r = g_h + (size_t)snd1*64;

    #pragma unroll
    for (int p = 0; p < 3; p++) {
        float D[8][4];
        #pragma unroll
        for (int ntl = 0; ntl < 8; ntl++) {
            D[ntl][0] = D[ntl][1] = D[ntl][2] = D[ntl][3] = 0.f;
            #pragma unroll
            for (int kt = 0; kt < 4; kt++) {
                uint4 wf = g_wfrag[(72 + kt*24 + p*8 + ntl)*32 + lane];
                mma16816(D[ntl], Ah[kt][0], Ah[kt][1], Ah[kt][2], Ah[kt][3], wf.x, wf.y);
                mma16816(D[ntl], Ah[kt][0], Ah[kt][1], Ah[kt][2], Ah[kt][3], wf.z, wf.w);
                mma16816(D[ntl], Al[kt][0], Al[kt][1], Al[kt][2], Al[kt][3], wf.x, wf.y);
            }
        }
        #pragma unroll
        for (int ntl = 0; ntl < 8; ntl++) {
            int col = 8*ntl + 2*tig;
            float2 h0 = *(const float2*)(h0r + col);
            float2 h1 = *(const float2*)(h1r + col);
            *(float2*)(tw + g*TROW + p*64 + col)     = make_float2(D[ntl][0]*h0.x, D[ntl][1]*h0.y);
            *(float2*)(tw + (g+8)*TROW + p*64 + col) = make_float2(D[ntl][2]*h1.x, D[ntl][3]*h1.y);
        }
    }

    // ---- SH + receiver ids -> smem (lanes 0..15, one sorted position each) ----
    if (lane < 16) {
        const int e = g_order[base + lane];
        float vx = vectors[e*3], vy = vectors[e*3+1], vz = vectors[e*3+2];
        float inv = rsqrtf(vx*vx + vy*vy + vz*vz);
        float ux = vx*inv, uy = vy*inv, uz = vz*inv;
        const float SQ3 = 1.7320508075688772f, S15 = 3.872983346207417f;
        const float HS5 = 1.118033988749895f;
        float* yr = yw + lane*8;
        yr[0] = SQ3*ux; yr[1] = SQ3*uy; yr[2] = SQ3*uz;
        yr[3] = S15*ux*uy; yr[4] = S15*uy*uz; yr[5] = HS5*(3.f*uz*uz - 1.f);
        yr[6] = S15*ux*uz; yr[7] = 0.5f*S15*(ux*ux - uy*uy);
        rcw[lane] = receivers[e];
    }
    __syncwarp();

    // ---- fused segmented reduction: lane owns channels c0, c0+1 across all 9 planes ----
    const int c0 = 2*lane;
    float acc[9][2];
    #pragma unroll
    for (int m = 0; m < 9; m++) { acc[m][0] = 0.f; acc[m][1] = 0.f; }
    int prev = rcw[0];

    #pragma unroll 1
    for (int r = 0; r < 16; r++) {
        int rc = rcw[r];
        if (rc != prev) {
            float* ab = g_agg + (size_t)prev*64 + c0;
            #pragma unroll
            for (int m = 0; m < 9; m++) {
                red2(ab + (size_t)m*PL, acc[m][0], acc[m][1]);
                acc[m][0] = 0.f; acc[m][1] = 0.f;
            }
            prev = rc;
        }
        const float* tr = tw + r*TROW;
        float2 t0 = *(const float2*)(tr + c0);
        float2 t1 = *(const float2*)(tr + 64 + c0);
        float2 t2 = *(const float2*)(tr + 128 + c0);
        const float* yr = yw + r*8;
        acc[0][0] += t0.x; acc[0][1] += t0.y;
        #pragma unroll
        for (int m = 0; m < 3; m++) {
            float ym = yr[m];
            acc[1+m][0] = fmaf(t1.x, ym, acc[1+m][0]);
            acc[1+m][1] = fmaf(t1.y, ym, acc[1+m][1]);
        }
        #pragma unroll
        for (int m = 0; m < 5; m++) {
            float ym = yr[3+m];
            acc[4+m][0] = fmaf(t2.x, ym, acc[4+m][0]);
            acc[4+m][1] = fmaf(t2.y, ym, acc[4+m][1]);
        }
    }
    {
        float* ab = g_agg + (size_t)prev*64 + c0;
        #pragma unroll
        for (int m = 0; m < 9; m++)
            red2(ab + (size_t)m*PL, acc[m][0], acc[m][1]);
    }
}

// ---------------------------------------------------------------- counting sort by receiver
__global__ void hist_kernel(const int* __restrict__ receivers) {
    int e = blockIdx.x * blockDim.x + threadIdx.x;
    if (e < NE) atomicAdd(&g_cnt[receivers[e]], 1);
}

__global__ void scan_kernel() {
    __shared__ int part[1024];
    const int t = threadIdx.x;
    const int base = t * 20;
    int sum = 0;
    if (t < 1000) {
        #pragma unroll
        for (int k = 0; k < 20; k++) sum += g_cnt[base + k];
    }
    part[t] = sum;
    __syncthreads();
    #pragma unroll
    for (int off = 1; off < 1024; off <<= 1) {
        int v = (t >= off) ? part[t - off] : 0;
        __syncthreads();
        part[t] += v;
        __syncthreads();
    }
    if (t < 1000) {
        int run = part[t] - sum;
        #pragma unroll
        for (int k = 0; k < 20; k++) {
            g_off[base + k] = run;
            g_cur[base + k] = run;
            run += g_cnt[base + k];
        }
    }
    if (t == 0) g_off[NN] = NE;
}

__global__ void order_kernel(const int* __restrict__ receivers) {
    int e = blockIdx.x * blockDim.x + threadIdx.x;
    if (e < NE) {
        int pos = atomicAdd(&g_cur[receivers[e]], 1);
        g_order[pos] = e;
    }
}

// ---------------------------------------------------------------- down projection
#define DGRP 79
__global__ __launch_bounds__(256) void down_kernel(const float* __restrict__ w0, const float* __restrict__ w1,
                                                   const float* __restrict__ w2, float* __restrict__ out)
{
    extern __shared__ float sm[];
    float* swp   = sm;            // 4096 floats
    float* tiles = sm + 4096;     // 8 * 32*65 floats

    const int plane = blockIdx.x / DGRP;
    const float* wsrc = (plane == 0) ? w0 : (plane < 4 ? w1 : w2);
    {
        float4* d = (float4*)swp; const float4* s = (const float4*)wsrc;
        for (int i = threadIdx.x; i < 1024; i += 256) d[i] = s[i];
    }
    __syncthreads();

    const int wid = threadIdx.x >> 5, lane = threadIdx.x & 31;
    const int grp = (blockIdx.x % DGRP) * 8 + wid;
    if (grp >= 625) return;
    const int n0 = grp * 32;

    float* tile = tiles + wid * (32*65);
    {
        const float4* src = (const float4*)(g_agg + (size_t)plane*PL + (size_t)n0*64);
        #pragma unroll
        for (int j = 0; j < 16; j++) {
            int idx = j*32 + lane;
            float4 v = src[idx];
            float* tp = tile + (idx >> 4)*65 + (idx & 15)*4;
            tp[0] = v.x; tp[1] = v.y; tp[2] = v.z; tp[3] = v.w;
        }
    }
    __syncwarp();

    const float* arow = tile + lane*65;
    ull acc[32];
    #pragma unroll
    for (int k = 0; k < 32; k++) acc[k] = 0ull;
    #pragma unroll
    for (int c = 0; c < 64; c++) {
        ull a2 = pack2(arow[c]);
        const ulonglong2* wr = (const ulonglong2*)(swp + c*64);
        #pragma unroll
        for (int t = 0; t < 16; t++) {
            ulonglong2 wp = wr[t];
            ffma2(acc[2*t],   wp.x, a2);
            ffma2(acc[2*t+1], wp.y, a2);
        }
    }

    const float S = 0.0625f;
    const int n = n0 + lane;
    float* ob = out + (size_t)n*576;
    if (plane == 0) {
        float4* o4 = (float4*)ob;
        #pragma unroll
        for (int k = 0; k < 16; k++) {
            float2 lo = unpk(acc[2*k]), hi = unpk(acc[2*k+1]);
            o4[k] = make_float4(lo.x*S, lo.y*S, hi.x*S, hi.y*S);
        }
    } else if (plane < 4) {
        float* b = ob + 64 + (plane - 1);
        #pragma unroll
        for (int k = 0; k < 32; k++) {
            float2 f = unpk(acc[k]);
            b[3*(2*k)]   = f.x * S;
            b[3*(2*k+1)] = f.y * S;
        }
    } else {
        float* b = ob + 256 + (plane - 4);
        #pragma unroll
        for (int k = 0; k < 32; k++) {
            float2 f = unpk(acc[k]);
            b[5*(2*k)]   = f.x * S;
            b[5*(2*k+1)] = f.y * S;
        }
    }
}

// ---------------------------------------------------------------- launch
extern "C" void kernel_launch(void* const* d_in, const int* in_sizes, int n_in,
                              void* d_out, int out_size)
{
    const float* vectors    = (const float*)d_in[0];
    const float* node_feats = (const float*)d_in[1];
    const float* radial     = (const float*)d_in[2];
    const int*   senders    = (const int*)  d_in[3];
    const int*   receivers  = (const int*)  d_in[4];
    const float* w_up       = (const float*)d_in[5];
    const float* mlp_w1     = (const float*)d_in[6];
    const float* mlp_w2     = (const float*)d_in[7];
    const float* mlp_w3     = (const float*)d_in[8];
    const float* mlp_w4     = (const float*)d_in[9];
    const float* w_down0    = (const float*)d_in[10];
    const float* w_down1    = (const float*)d_in[11];
    const float* w_down2    = (const float*)d_in[12];
    float* out = (float*)d_out;

    const int D_SMEM = (4096 + 8*32*65) * 4;
    const int E_SMEM = ESMEM_F * 4;
    cudaFuncSetAttribute(down_kernel,  cudaFuncAttributeMaxDynamicSharedMemorySize, D_SMEM);
    cudaFuncSetAttribute(edgeM_kernel, cudaFuncAttributeMaxDynamicSharedMemorySize, E_SMEM);

    void* cntp = nullptr;
    cudaGetSymbolAddress(&cntp, g_cnt);
    cudaMemsetAsync(cntp, 0, NN * sizeof(int));
    void* aggp = nullptr;
    cudaGetSymbolAddress(&aggp, g_agg);
    cudaMemsetAsync(aggp, 0, (size_t)9 * PL * sizeof(float));

    hist_kernel<<<(NE + 255)/256, 256>>>(receivers);
    scan_kernel<<<1, 1024>>>();
    order_kernel<<<(NE + 255)/256, 256>>>(receivers);
    prep_kernel<<<168, 32>>>(mlp_w1, mlp_w2, mlp_w3, mlp_w4);
    up_kernel<<<NN/4, 256>>>(node_feats, w_up);
    edgeM_kernel<<<NE/(16*4), 128, E_SMEM>>>(vectors, radial, senders, receivers);
    down_kernel<<<9*DGRP, 256, D_SMEM>>>(w_down0, w_down1, w_down2, out);
}

// round 10
// speedup vs baseline: 8.2892x; 1.2498x over previous
#include <cuda_runtime.h>
#include <cuda_bf16.h>
#include <cstdint>

#define NN 20000
#define NE 320000
#define CC 64
#define PL (NN*CC)

typedef unsigned long long ull;

// Scratch (allocation-free rule: __device__ globals)
__device__ __align__(16) float g_h[NN*CC];        // 5.1 MB
__device__ __align__(16) float g_agg[9*PL];       // 46 MB (atomic target, planar)
__device__ __align__(16) uint4 g_wfrag[264*32];   // 135 KB packed B fragments (MLP + down)
__device__ int g_cnt[NN];
__device__ int g_off[NN+1];
__device__ int g_cur[NN];
__device__ int g_order[NE];

// silu via hardware tanh: x*sigmoid(x) = 0.5x*tanh(0.5x) + 0.5x
__device__ __forceinline__ float silu(float x) {
    float hx = 0.5f * x;
    float t;
    asm("tanh.approx.f32 %0, %1;" : "=f"(t) : "f"(hx));
    return fmaf(hx, t, hx);
}
__device__ __forceinline__ void red2(float* p, float a, float b) {
    asm volatile("red.global.add.v2.f32 [%0], {%1,%2};" :: "l"(p), "f"(a), "f"(b) : "memory");
}

// pack (x0 -> low half, x1 -> high half) as bf16x2; return hi-word, write lo(residual)-word
__device__ __forceinline__ uint32_t split_pair(float x0, float x1, uint32_t& lw) {
    uint32_t hw;
    asm("cvt.rn.bf16x2.f32 %0, %1, %2;" : "=r"(hw) : "f"(x1), "f"(x0));
    float h0 = __uint_as_float(hw << 16);
    float h1 = __uint_as_float(hw & 0xffff0000u);
    asm("cvt.rn.bf16x2.f32 %0, %1, %2;" : "=r"(lw) : "f"(x1 - h1), "f"(x0 - h0));
    return hw;
}

__device__ __forceinline__ void mma16816(float c[4],
    uint32_t a0, uint32_t a1, uint32_t a2, uint32_t a3, uint32_t b0, uint32_t b1)
{
    asm volatile("mma.sync.aligned.m16n8k16.row.col.f32.bf16.bf16.f32 "
        "{%0,%1,%2,%3},{%4,%5,%6,%7},{%8,%9},{%0,%1,%2,%3};"
        : "+f"(c[0]), "+f"(c[1]), "+f"(c[2]), "+f"(c[3])
        : "r"(a0), "r"(a1), "r"(a2), "r"(a3), "r"(b0), "r"(b1));
}

// ---------------------------------------------------------------- fused init:
// blocks [0,264): pack one B-fragment tile each (threads 0..31) + zero g_cnt
// blocks [264, 264+5000): up-projection h = nf @ w_up / 8
// tile map: [0,8) L1 ; [8,40) L2 ; [40,72) L3 ; [72,168) L4 ; [168,200) down0 ; [200,232) down1 ; [232,264) down2
__global__ __launch_bounds__(256) void init_kernel(
    const float* __restrict__ nf, const float* __restrict__ wup,
    const float* __restrict__ w1, const float* __restrict__ w2,
    const float* __restrict__ w3, const float* __restrict__ w4,
    const float* __restrict__ wd0, const float* __restrict__ wd1,
    const float* __restrict__ wd2)
{
    if (blockIdx.x < 264) {
        // zero g_cnt
        int zi = blockIdx.x * 256 + threadIdx.x;
        if (zi < NN) g_cnt[zi] = 0;
        if (threadIdx.x < 32) {
            const int tile = blockIdx.x;
            const int lane = threadIdx.x;
            const int g = lane >> 2, tig = lane & 3;
            const float* W; int K, Nc, kt, nt; float sc;
            if (tile < 8)        { W = w1;  K = 8;  Nc = 64;  kt = 0;      nt = tile;    sc = 0.35355339059f; }
            else if (tile < 40)  { int t = tile-8;   W = w2;  K = 64; Nc = 64;  kt = t >> 3; nt = t & 7;  sc = 0.125f; }
            else if (tile < 72)  { int t = tile-40;  W = w3;  K = 64; Nc = 64;  kt = t >> 3; nt = t & 7;  sc = 0.125f; }
            else if (tile < 168) { int t = tile-72;  W = w4;  K = 64; Nc = 192; kt = t / 24; nt = t % 24; sc = 0.001953125f; }
            else if (tile < 200) { int t = tile-168; W = wd0; K = 64; Nc = 64;  kt = t >> 3; nt = t & 7;  sc = 0.0625f; }
            else if (tile < 232) { int t = tile-200; W = wd1; K = 64; Nc = 64;  kt = t >> 3; nt = t & 7;  sc = 0.0625f; }
            else                 { int t = tile-232; W = wd2; K = 64; Nc = 64;  kt = t >> 3; nt = t & 7;  sc = 0.0625f; }
            const int n = nt*8 + g;
            const int k0 = kt*16 + 2*tig;
            float x00 = (k0   < K) ? W[(k0  )*Nc + n]*sc : 0.f;
            float x01 = (k0+1 < K) ? W[(k0+1)*Nc + n]*sc : 0.f;
            float x10 = (k0+8 < K) ? W[(k0+8)*Nc + n]*sc : 0.f;
            float x11 = (k0+9 < K) ? W[(k0+9)*Nc + n]*sc : 0.f;
            uint32_t l0, l1;
            uint32_t h0 = split_pair(x00, x01, l0);
            uint32_t h1 = split_pair(x10, x11, l1);
            g_wfrag[tile*32 + lane] = make_uint4(h0, h1, l0, l1);
        }
        return;
    }
    // ---- up projection ----
    __shared__ float ws[CC*CC];
    __shared__ float rows[4*CC];
    const int ub = blockIdx.x - 264;
    for (int i = threadIdx.x; i < CC*CC; i += 256) ws[i] = wup[i];
    int base = ub * 4 * CC;
    rows[threadIdx.x] = nf[base + threadIdx.x];
    __syncthreads();
    int r = threadIdx.x >> 6;
    int c = threadIdx.x & 63;
    float acc = 0.f;
    #pragma unroll
    for (int i = 0; i < CC; i++) acc = fmaf(rows[r*CC + i], ws[i*CC + c], acc);
    g_h[base + threadIdx.x] = acc * 0.125f;
}

// ---------------------------------------------------------------- shared mma helpers
__device__ __forceinline__ void layerK64(int tbase, int lane, float C[8][4],
                                         const uint32_t Ah[4][4], const uint32_t Al[4][4])
{
    #pragma unroll
    for (int nt = 0; nt < 8; nt++) {
        C[nt][0] = C[nt][1] = C[nt][2] = C[nt][3] = 0.f;
        #pragma unroll
        for (int kt = 0; kt < 4; kt++) {
            uint4 wf = g_wfrag[(tbase + kt*8 + nt)*32 + lane];
            mma16816(C[nt], Ah[kt][0], Ah[kt][1], Ah[kt][2], Ah[kt][3], wf.x, wf.y);
            mma16816(C[nt], Ah[kt][0], Ah[kt][1], Ah[kt][2], Ah[kt][3], wf.z, wf.w);
            mma16816(C[nt], Al[kt][0], Al[kt][1], Al[kt][2], Al[kt][3], wf.x, wf.y);
        }
    }
}

__device__ __forceinline__ void transition(const float C[8][4], uint32_t Ah[4][4], uint32_t Al[4][4])
{
    #pragma unroll
    for (int kt = 0; kt < 4; kt++) {
        const float* ca = C[2*kt];
        const float* cb = C[2*kt+1];
        Ah[kt][0] = split_pair(silu(ca[0]), silu(ca[1]), Al[kt][0]);
        Ah[kt][1] = split_pair(silu(ca[2]), silu(ca[3]), Al[kt][1]);
        Ah[kt][2] = split_pair(silu(cb[0]), silu(cb[1]), Al[kt][2]);
        Ah[kt][3] = split_pair(silu(cb[2]), silu(cb[3]), Al[kt][3]);
    }
}

// tile row stride (floats)
#define TROW 194
#define TILE_F (16*TROW)
#define EY_OFF (4*TILE_F)
#define ESMEM_F (4*TILE_F + 4*128 + 4*16)

// ---------------------------------------------------------------- edgeM: MLP (mma) + fused segmented scatter
__global__ __launch_bounds__(128) void edgeM_kernel(
    const float* __restrict__ vectors, const float* __restrict__ radial,
    const int* __restrict__ senders, const int* __restrict__ receivers)
{
    extern __shared__ float esm[];
    const int wid = threadIdx.x >> 5;
    const int lane = threadIdx.x & 31;
    float* tw = esm + wid*TILE_F;
    float* yw = esm + EY_OFF + wid*128;
    int*   rcw = (int*)(esm + EY_OFF + 4*128) + wid*16;

    const int wt = blockIdx.x*4 + wid;
    const int g = lane >> 2, tig = lane & 3;
    const int base = wt*16;
    const int p0 = base + g, p1 = p0 + 8;
    const int e0 = g_order[p0], e1 = g_order[p1];

    uint32_t Ah[4][4], Al[4][4];
    {
        float2 r0 = *(const float2*)(radial + (size_t)e0*8 + 2*tig);
        float2 r1 = *(const float2*)(radial + (size_t)e1*8 + 2*tig);
        Ah[0][0] = split_pair(r0.x, r0.y, Al[0][0]);
        Ah[0][1] = split_pair(r1.x, r1.y, Al[0][1]);
        Ah[0][2] = 0; Ah[0][3] = 0; Al[0][2] = 0; Al[0][3] = 0;
    }

    float C[8][4];
    // ---- L1 ----
    #pragma unroll
    for (int nt = 0; nt < 8; nt++) {
        C[nt][0] = C[nt][1] = C[nt][2] = C[nt][3] = 0.f;
        uint4 wf = g_wfrag[nt*32 + lane];
        mma16816(C[nt], Ah[0][0], Ah[0][1], Ah[0][2], Ah[0][3], wf.x, wf.y);
        mma16816(C[nt], Ah[0][0], Ah[0][1], Ah[0][2], Ah[0][3], wf.z, wf.w);
        mma16816(C[nt], Al[0][0], Al[0][1], Al[0][2], Al[0][3], wf.x, wf.y);
    }
    transition(C, Ah, Al);
    layerK64(8, lane, C, Ah, Al);    // L2
    transition(C, Ah, Al);
    layerK64(40, lane, C, Ah, Al);   // L3
    transition(C, Ah, Al);

    // ---- L4 (N=192) -> smem tile ----
    const int snd0 = senders[e0], snd1 = senders[e1];
    const float* h0r = g_h + (size_t)snd0*64;
    const float* h1r = g_h + (size_t)snd1*64;

    #pragma unroll
    for (int p = 0; p < 3; p++) {
        float D[8][4];
        #pragma unroll
        for (int ntl = 0; ntl < 8; ntl++) {
            D[ntl][0] = D[ntl][1] = D[ntl][2] = D[ntl][3] = 0.f;
            #pragma unroll
            for (int kt = 0; kt < 4; kt++) {
                uint4 wf = g_wfrag[(72 + kt*24 + p*8 + ntl)*32 + lane];
                mma16816(D[ntl], Ah[kt][0], Ah[kt][1], Ah[kt][2], Ah[kt][3], wf.x, wf.y);
                mma16816(D[ntl], Ah[kt][0], Ah[kt][1], Ah[kt][2], Ah[kt][3], wf.z, wf.w);
                mma16816(D[ntl], Al[kt][0], Al[kt][1], Al[kt][2], Al[kt][3], wf.x, wf.y);
            }
        }
        #pragma unroll
        for (int ntl = 0; ntl < 8; ntl++) {
            int col = 8*ntl + 2*tig;
            float2 h0 = *(const float2*)(h0r + col);
            float2 h1 = *(const float2*)(h1r + col);
            *(float2*)(tw + g*TROW + p*64 + col)     = make_float2(D[ntl][0]*h0.x, D[ntl][1]*h0.y);
            *(float2*)(tw + (g+8)*TROW + p*64 + col) = make_float2(D[ntl][2]*h1.x, D[ntl][3]*h1.y);
        }
    }

    // ---- SH + receiver ids -> smem ----
    if (lane < 16) {
        const int e = g_order[base + lane];
        float vx = vectors[e*3], vy = vectors[e*3+1], vz = vectors[e*3+2];
        float inv = rsqrtf(vx*vx + vy*vy + vz*vz);
        float ux = vx*inv, uy = vy*inv, uz = vz*inv;
        const float SQ3 = 1.7320508075688772f, S15 = 3.872983346207417f;
        const float HS5 = 1.118033988749895f;
        float* yr = yw + lane*8;
        yr[0] = SQ3*ux; yr[1] = SQ3*uy; yr[2] = SQ3*uz;
        yr[3] = S15*ux*uy; yr[4] = S15*uy*uz; yr[5] = HS5*(3.f*uz*uz - 1.f);
        yr[6] = S15*ux*uz; yr[7] = 0.5f*S15*(ux*ux - uy*uy);
        rcw[lane] = receivers[e];
    }
    __syncwarp();

    // ---- fused segmented reduction ----
    const int c0 = 2*lane;
    float acc[9][2];
    #pragma unroll
    for (int m = 0; m < 9; m++) { acc[m][0] = 0.f; acc[m][1] = 0.f; }
    int prev = rcw[0];

    #pragma unroll 1
    for (int r = 0; r < 16; r++) {
        int rc = rcw[r];
        if (rc != prev) {
            float* ab = g_agg + (size_t)prev*64 + c0;
            #pragma unroll
            for (int m = 0; m < 9; m++) {
                red2(ab + (size_t)m*PL, acc[m][0], acc[m][1]);
                acc[m][0] = 0.f; acc[m][1] = 0.f;
            }
            prev = rc;
        }
        const float* tr = tw + r*TROW;
        float2 t0 = *(const float2*)(tr + c0);
        float2 t1 = *(const float2*)(tr + 64 + c0);
        float2 t2 = *(const float2*)(tr + 128 + c0);
        const float* yr = yw + r*8;
        acc[0][0] += t0.x; acc[0][1] += t0.y;
        #pragma unroll
        for (int m = 0; m < 3; m++) {
            float ym = yr[m];
            acc[1+m][0] = fmaf(t1.x, ym, acc[1+m][0]);
            acc[1+m][1] = fmaf(t1.y, ym, acc[1+m][1]);
        }
        #pragma unroll
        for (int m = 0; m < 5; m++) {
            float ym = yr[3+m];
            acc[4+m][0] = fmaf(t2.x, ym, acc[4+m][0]);
            acc[4+m][1] = fmaf(t2.y, ym, acc[4+m][1]);
        }
    }
    {
        float* ab = g_agg + (size_t)prev*64 + c0;
        #pragma unroll
        for (int m = 0; m < 9; m++)
            red2(ab + (size_t)m*PL, acc[m][0], acc[m][1]);
    }
}

// ---------------------------------------------------------------- counting sort by receiver
__global__ void hist_kernel(const int* __restrict__ receivers) {
    int e = blockIdx.x * blockDim.x + threadIdx.x;
    if (e < NE) atomicAdd(&g_cnt[receivers[e]], 1);
}

__global__ void scan_kernel() {
    __shared__ int part[1024];
    const int t = threadIdx.x;
    const int base = t * 20;
    int sum = 0;
    if (t < 1000) {
        #pragma unroll
        for (int k = 0; k < 20; k++) sum += g_cnt[base + k];
    }
    part[t] = sum;
    __syncthreads();
    #pragma unroll
    for (int off = 1; off < 1024; off <<= 1) {
        int v = (t >= off) ? part[t - off] : 0;
        __syncthreads();
        part[t] += v;
        __syncthreads();
    }
    if (t < 1000) {
        int run = part[t] - sum;
        #pragma unroll
        for (int k = 0; k < 20; k++) {
            g_off[base + k] = run;
            g_cur[base + k] = run;
            run += g_cnt[base + k];
        }
    }
    if (t == 0) g_off[NN] = NE;
}

__global__ void order_kernel(const int* __restrict__ receivers) {
    int e = blockIdx.x * blockDim.x + threadIdx.x;
    if (e < NE) {
        int pos = atomicAdd(&g_cur[receivers[e]], 1);
        g_order[pos] = e;
    }
}

// ---------------------------------------------------------------- down projection via mma
// warp job = (plane, 16-node tile). A = agg rows (2-term split), B = packed w_down frags.
#define NJOBS (9*1250)
__global__ __launch_bounds__(128) void downM_kernel(float* __restrict__ out)
{
    const int job = blockIdx.x*4 + (threadIdx.x >> 5);
    if (job >= NJOBS) return;
    const int lane = threadIdx.x & 31;
    const int g = lane >> 2, tig = lane & 3;
    const int plane = job / 1250;
    const int n0 = (job - plane*1250) * 16;

    const float* ar = g_agg + (size_t)plane*PL;
    uint32_t Ah[4][4], Al[4][4];
    #pragma unroll
    for (int kt = 0; kt < 4; kt++) {
        const int c0 = kt*16 + 2*tig;
        const float* r0p = ar + (size_t)(n0+g)*64 + c0;
        const float* r1p = ar + (size_t)(n0+g+8)*64 + c0;
        float2 a00 = *(const float2*)(r0p);
        float2 a01 = *(const float2*)(r0p + 8);
        float2 a10 = *(const float2*)(r1p);
        float2 a11 = *(const float2*)(r1p + 8);
        Ah[kt][0] = split_pair(a00.x, a00.y, Al[kt][0]);
        Ah[kt][1] = split_pair(a10.x, a10.y, Al[kt][1]);
        Ah[kt][2] = split_pair(a01.x, a01.y, Al[kt][2]);
        Ah[kt][3] = split_pair(a11.x, a11.y, Al[kt][3]);
    }

    const int tbase = 168 + (plane == 0 ? 0 : (plane < 4 ? 32 : 64));
    float C[8][4];
    layerK64(tbase, lane, C, Ah, Al);

    // stores (EPS * inv_sqrt_c already folded into weight scale)
    float* ob0 = out + (size_t)(n0+g)*576;
    float* ob1 = out + (size_t)(n0+g+8)*576;
    if (plane == 0) {
        #pragma unroll
        for (int nt = 0; nt < 8; nt++) {
            int d = 8*nt + 2*tig;
            *(float2*)(ob0 + d) = make_float2(C[nt][0], C[nt][1]);
            *(float2*)(ob1 + d) = make_float2(C[nt][2], C[nt][3]);
        }
    } else if (plane < 4) {
        float* b0 = ob0 + 64 + (plane - 1);
        float* b1 = ob1 + 64 + (plane - 1);
        #pragma unroll
        for (int nt = 0; nt < 8; nt++) {
            int d = 8*nt + 2*tig;
            b0[3*d] = C[nt][0]; b0[3*(d+1)] = C[nt][1];
            b1[3*d] = C[nt][2]; b1[3*(d+1)] = C[nt][3];
        }
    } else {
        float* b0 = ob0 + 256 + (plane - 4);
        float* b1 = ob1 + 256 + (plane - 4);
        #pragma unroll
        for (int nt = 0; nt < 8; nt++) {
            int d = 8*nt + 2*tig;
            b0[5*d] = C[nt][0]; b0[5*(d+1)] = C[nt][1];
            b1[5*d] = C[nt][2]; b1[5*(d+1)] = C[nt][3];
        }
    }
}

// ---------------------------------------------------------------- launch
extern "C" void kernel_launch(void* const* d_in, const int* in_sizes, int n_in,
                              void* d_out, int out_size)
{
    const float* vectors    = (const float*)d_in[0];
    const float* node_feats = (const float*)d_in[1];
    const float* radial     = (const float*)d_in[2];
    const int*   senders    = (const int*)  d_in[3];
    const int*   receivers  = (const int*)  d_in[4];
    const float* w_up       = (const float*)d_in[5];
    const float* mlp_w1     = (const float*)d_in[6];
    const float* mlp_w2     = (const float*)d_in[7];
    const float* mlp_w3     = (const float*)d_in[8];
    const float* mlp_w4     = (const float*)d_in[9];
    const float* w_down0    = (const float*)d_in[10];
    const float* w_down1    = (const float*)d_in[11];
    const float* w_down2    = (const float*)d_in[12];
    float* out = (float*)d_out;

    const int E_SMEM = ESMEM_F * 4;
    cudaFuncSetAttribute(edgeM_kernel, cudaFuncAttributeMaxDynamicSharedMemorySize, E_SMEM);

    void* aggp = nullptr;
    cudaGetSymbolAddress(&aggp, g_agg);
    cudaMemsetAsync(aggp, 0, (size_t)9 * PL * sizeof(float));                 // launch 1

    init_kernel<<<264 + NN/4, 256>>>(node_feats, w_up, mlp_w1, mlp_w2,        // launch 2
                                     mlp_w3, mlp_w4, w_down0, w_down1, w_down2);
    hist_kernel<<<(NE + 255)/256, 256>>>(receivers);                          // launch 3
    scan_kernel<<<1, 1024>>>();                                               // launch 4
    order_kernel<<<(NE + 255)/256, 256>>>(receivers);                         // launch 5
    edgeM_kernel<<<NE/(16*4), 128, E_SMEM>>>(vectors, radial, senders, receivers); // launch 6 (ncu -s 5 -c 1)
    downM_kernel<<<(NJOBS + 3)/4, 128>>>(out);                                // launch 7
}